// round 15
// baseline (speedup 1.0000x reference)
#include <cuda_runtime.h>

#define NB 512
#define PPAR 128
#define NN 65536
#define NE 524288
#define CAP 48

// ---------------- scratch (device globals; no allocation) ----------------
__device__ int   g_cnt[NN];
__device__ unsigned char g_slot[(size_t)NN * CAP];
__device__ float g_hrs[NB * 128];
__device__ float g_part[16 * NB * 128];
__device__ float g_pool[NB * 128];
__device__ float g_F[NB * 256];
__device__ float g_med[NB * NB];     // fallback if out buffer lacks med space
__device__ float g_dinv[NB];
__device__ int   g_nnz[NB];
__device__ int   g_nbr[NB * NB];
__device__ float g_AH[NB * 256];
__device__ float g_hrsagg[NB * 128];
__device__ float g_poiagg[NB * 128];
__device__ float g_ph[NB * 128];
__device__ float g_u[3 * 128];
__device__ float g_rv[3 * 128];
__device__ float g_ch[3];
__device__ float g_p2i[NB * 128];
__device__ float g_i2p[NB * 128];
__device__ float g_wavg[128 * 128];
__device__ float g_bavg[128];

// ---------------- zero counts (int4) + wavg/bavg (fused) ----------------
__global__ void k_zero(const float* __restrict__ Wg_w, const float* __restrict__ bg_w) {
    int i = blockIdx.x * blockDim.x + threadIdx.x;   // 16384 threads
    if (i < NN / 4) ((int4*)g_cnt)[i] = make_int4(0, 0, 0, 0);
    if (i < 128 * 128) {
        int k = i >> 7, c = i & 127;
        g_wavg[i] = (Wg_w[k * 384 + c] + Wg_w[k * 384 + 128 + c] + Wg_w[k * 384 + 256 + c])
                    * (1.f / 3.f);
    }
    if (i < 128)
        g_bavg[i] = (bg_w[i] + bg_w[128 + i] + bg_w[256 + i]) * (1.f / 3.f);
}

__global__ void k_scatter(const int* __restrict__ src, const int* __restrict__ dst) {
    int idx = blockIdx.x * blockDim.x + threadIdx.x;   // NE/4 threads
    if (idx < NE / 4) {
        int4 s4 = ((const int4*)src)[idx];
        int4 d4 = ((const int4*)dst)[idx];
        int ss[4] = {s4.x, s4.y, s4.z, s4.w};
        int dd[4] = {d4.x, d4.y, d4.z, d4.w};
        #pragma unroll
        for (int q = 0; q < 4; q++) {
            int d = dd[q];
            int pos = atomicAdd(&g_cnt[d], 1);
            if (pos < CAP)
                g_slot[(size_t)d * CAP + pos] = (unsigned char)(ss[q] & 127);
        }
    }
}

// ---------------- MEGA: gcn1 + gcn2 + pool + F-normalize + GAT + p2i ----------------
// 2 regions, 100KB dyn smem, 2 CTAs/SM.
__global__ void __launch_bounds__(256, 2)
k_mega(const float* __restrict__ poi_x,
       const float* __restrict__ W1, const float* __restrict__ b1,
       const float* __restrict__ W2, const float* __restrict__ b2,
       const float* __restrict__ Wpp, const float* __restrict__ bpp,
       const float* __restrict__ Wg_in, const float* __restrict__ bg_in) {
    extern __shared__ float sm[];
    float* A = sm;
    float* C = sm + 128 * 132;
    __shared__ float snrm[128];
    __shared__ int scnt[128];
    __shared__ float shm[3], shs[3], sher[3], shc[3];
    const int tid = threadIdx.x;
    const int blk = blockIdx.x;
    const int base = blk * 128;

    if (tid < 128) {
        int c = g_cnt[base + tid];
        snrm[tid] = rsqrtf((float)c + 1.0f);
        scnt[tid] = (c > CAP) ? CAP : c;
    }
    {   // W1 -> C (64x128)
        const float4* W4 = (const float4*)W1;
        float4* C4 = (float4*)C;
        for (int i = tid; i < 64 * 32; i += 256) C4[i] = W4[i];
    }
    __syncthreads();
    {   // X * norm -> A (stride 68)
        const float4* in4 = (const float4*)(poi_x + (size_t)base * 64);
        for (int i = tid; i < 128 * 16; i += 256) {
            int r = i >> 4, c4 = i & 15;
            float4 v = in4[i];
            float nr = snrm[r];
            v.x *= nr; v.y *= nr; v.z *= nr; v.w *= nr;
            *(float4*)&A[r * 68 + c4 * 4] = v;
        }
    }
    __syncthreads();
    const int d = tid >> 1;
    const int tr = tid >> 4, tc = tid & 15;
    const int r0 = tr * 8, cc0 = tc * 8;

    // ---- agg1 (K=64) into registers ----
    {
        const int c0 = (tid & 1) * 32;
        float racc[32];
        #pragma unroll
        for (int q = 0; q < 8; q++) {
            float4 v = *(const float4*)&A[d * 68 + c0 + q * 4];
            racc[q * 4 + 0] = v.x; racc[q * 4 + 1] = v.y;
            racc[q * 4 + 2] = v.z; racc[q * 4 + 3] = v.w;
        }
        const int cnt = scnt[d];
        const unsigned char* sl = g_slot + (size_t)(base + d) * CAP;
        for (int e = 0; e < cnt; e++) {
            int s = sl[e];
            #pragma unroll
            for (int q = 0; q < 8; q++) {
                float4 v = *(const float4*)&A[s * 68 + c0 + q * 4];
                racc[q * 4 + 0] += v.x; racc[q * 4 + 1] += v.y;
                racc[q * 4 + 2] += v.z; racc[q * 4 + 3] += v.w;
            }
        }
        float nr = snrm[d];
        __syncthreads();   // all X reads done -> safe to overwrite A
        #pragma unroll
        for (int c = 0; c < 32; c++) A[(c0 + c) * 132 + d] = racc[c] * nr;   // AGt1
    }
    __syncthreads();

    float vacc[8][8];
    // ---- GEMM1: vacc = AGt1(A) @ W1(C) ----
    #pragma unroll
    for (int i = 0; i < 8; i++)
        #pragma unroll
        for (int j = 0; j < 8; j++) vacc[i][j] = 0.f;
    for (int k = 0; k < 64; k++) {
        float4 a0 = *(const float4*)&A[k * 132 + r0];
        float4 a1 = *(const float4*)&A[k * 132 + r0 + 4];
        float4 b0 = *(const float4*)&C[k * 128 + cc0];
        float4 b1v = *(const float4*)&C[k * 128 + cc0 + 4];
        float av[8] = {a0.x, a0.y, a0.z, a0.w, a1.x, a1.y, a1.z, a1.w};
        float bv[8] = {b0.x, b0.y, b0.z, b0.w, b1v.x, b1v.y, b1v.z, b1v.w};
        #pragma unroll
        for (int i = 0; i < 8; i++)
            #pragma unroll
            for (int j = 0; j < 8; j++) vacc[i][j] += av[i] * bv[j];
    }
    __syncthreads();   // AGt1 + W1 reads done
    {   // h1 = relu(vacc + b1) * snrm[row] -> A
        float bv[8];
        #pragma unroll
        for (int j = 0; j < 8; j++) bv[j] = b1[cc0 + j];
        #pragma unroll
        for (int i = 0; i < 8; i++) {
            float nr2 = snrm[r0 + i];
            #pragma unroll
            for (int j = 0; j < 8; j++)
                vacc[i][j] = fmaxf(vacc[i][j] + bv[j], 0.f) * nr2;
            float4 o0 = {vacc[i][0], vacc[i][1], vacc[i][2], vacc[i][3]};
            float4 o1 = {vacc[i][4], vacc[i][5], vacc[i][6], vacc[i][7]};
            *(float4*)&A[(r0 + i) * 132 + cc0] = o0;
            *(float4*)&A[(r0 + i) * 132 + cc0 + 4] = o1;
        }
    }
    __syncthreads();   // h1 visible

    // ---- W2 half1 -> C, agg2 (K=128) into registers ----
    {
        const float4* W4 = (const float4*)W2;
        float4* C4 = (float4*)C;
        for (int i = tid; i < 64 * 32; i += 256) C4[i] = W4[i];
    }
    {
        const int c0 = (tid & 1) * 64;
        float racc[64];
        #pragma unroll
        for (int q = 0; q < 16; q++) {
            float4 v = *(const float4*)&A[d * 132 + c0 + q * 4];
            racc[q * 4 + 0] = v.x; racc[q * 4 + 1] = v.y;
            racc[q * 4 + 2] = v.z; racc[q * 4 + 3] = v.w;
        }
        const int cnt = scnt[d];
        const unsigned char* sl = g_slot + (size_t)(base + d) * CAP;
        for (int e = 0; e < cnt; e++) {
            int s = sl[e];
            #pragma unroll
            for (int q = 0; q < 16; q++) {
                float4 v = *(const float4*)&A[s * 132 + c0 + q * 4];
                racc[q * 4 + 0] += v.x; racc[q * 4 + 1] += v.y;
                racc[q * 4 + 2] += v.z; racc[q * 4 + 3] += v.w;
            }
        }
        float nr = snrm[d];
        __syncthreads();   // all h1 reads done -> safe to overwrite A
        #pragma unroll
        for (int c = 0; c < 64; c++) A[(c0 + c) * 132 + d] = racc[c] * nr;   // AGt2
    }
    __syncthreads();

    // ---- GEMM2 pass1: k = 0..63 ----
    #pragma unroll
    for (int i = 0; i < 8; i++)
        #pragma unroll
        for (int j = 0; j < 8; j++) vacc[i][j] = 0.f;
    for (int k = 0; k < 64; k++) {
        float4 a0 = *(const float4*)&A[k * 132 + r0];
        float4 a1 = *(const float4*)&A[k * 132 + r0 + 4];
        float4 b0 = *(const float4*)&C[k * 128 + cc0];
        float4 b1v = *(const float4*)&C[k * 128 + cc0 + 4];
        float av[8] = {a0.x, a0.y, a0.z, a0.w, a1.x, a1.y, a1.z, a1.w};
        float bv[8] = {b0.x, b0.y, b0.z, b0.w, b1v.x, b1v.y, b1v.z, b1v.w};
        #pragma unroll
        for (int i = 0; i < 8; i++)
            #pragma unroll
            for (int j = 0; j < 8; j++) vacc[i][j] += av[i] * bv[j];
    }
    __syncthreads();
    {   // W2 half2 -> C
        const float4* W4 = (const float4*)(W2 + 64 * 128);
        float4* C4 = (float4*)C;
        for (int i = tid; i < 64 * 32; i += 256) C4[i] = W4[i];
    }
    __syncthreads();
    // ---- GEMM2 pass2: k = 64..127 ----
    for (int k = 64; k < 128; k++) {
        float4 a0 = *(const float4*)&A[k * 132 + r0];
        float4 a1 = *(const float4*)&A[k * 132 + r0 + 4];
        float4 b0 = *(const float4*)&C[(k - 64) * 128 + cc0];
        float4 b1v = *(const float4*)&C[(k - 64) * 128 + cc0 + 4];
        float av[8] = {a0.x, a0.y, a0.z, a0.w, a1.x, a1.y, a1.z, a1.w};
        float bv[8] = {b0.x, b0.y, b0.z, b0.w, b1v.x, b1v.y, b1v.z, b1v.w};
        #pragma unroll
        for (int i = 0; i < 8; i++)
            #pragma unroll
            for (int j = 0; j < 8; j++) vacc[i][j] += av[i] * bv[j];
    }
    __syncthreads();
    {   // poi = vacc + b2 -> A
        float bv[8];
        #pragma unroll
        for (int j = 0; j < 8; j++) bv[j] = b2[cc0 + j];
        #pragma unroll
        for (int i = 0; i < 8; i++) {
            #pragma unroll
            for (int j = 0; j < 8; j++) vacc[i][j] += bv[j];
            float4 o0 = {vacc[i][0], vacc[i][1], vacc[i][2], vacc[i][3]};
            float4 o1 = {vacc[i][4], vacc[i][5], vacc[i][6], vacc[i][7]};
            *(float4*)&A[(r0 + i) * 132 + cc0] = o0;
            *(float4*)&A[(r0 + i) * 132 + cc0 + 4] = o1;
        }
    }
    __syncthreads();

    // ---- scratch layout in C ----
    float* P   = C;          // [16][128]
    float* us  = C + 2048;   // 384
    float* rvs = C + 2432;   // 384
    float* phs = C + 2816;   // 128
    float* se  = C + 2944;   // 384
    float* ts  = C + 3328;   // 384
    float* qs  = C + 3712;   // 384
    float* fv  = C + 4096;   // 256
    float* red = C + 4352;   // 256
    float* zb  = C;          // alias P

    #pragma unroll
    for (int j = 0; j < 8; j++) {
        float s = 0.f;
        #pragma unroll
        for (int i = 0; i < 8; i++) s += vacc[i][j];
        P[tr * 128 + cc0 + j] = s;
    }
    for (int i = tid; i < 384; i += 256) { us[i] = g_u[i]; rvs[i] = g_rv[i]; }
    if (tid < 128) phs[tid] = g_ph[blk * 128 + tid];
    if (tid < 3) shc[tid] = g_ch[tid];
    __syncthreads();
    if (tid < 128) {
        float s = 0.f;
        #pragma unroll
        for (int r = 0; r < 16; r++) s += P[r * 128 + tid];
        float pv = s * (1.f / 128.f);
        g_pool[blk * 128 + tid] = pv;
        fv[128 + tid] = pv;
        fv[tid] = g_hrs[blk * 128 + tid];
    }
    if (tid < 96) {
        int h = tid >> 5, lane = tid & 31;
        float s = 0.f;
        for (int j = lane; j < 128; j += 32) s += phs[j] * rvs[h * 128 + j];
        for (int off = 16; off > 0; off >>= 1) s += __shfl_down_sync(0xffffffffu, s, off);
        if (lane == 0) sher[h] = s;
    }
    __syncthreads();
    {
        float v = fv[tid];
        red[tid] = v * v;
        __syncthreads();
        for (int off = 128; off > 0; off >>= 1) {
            if (tid < off) red[tid] += red[tid + off];
            __syncthreads();
        }
        float inv = rsqrtf(red[0]);
        g_F[blk * 256 + tid] = v * inv;
    }

    if (tid < 128) {
        float a0 = 0.f, a1 = 0.f, a2 = 0.f;
        #pragma unroll
        for (int q = 0; q < 32; q++) {
            float4 x = *(const float4*)&A[tid * 132 + q * 4];
            float4 u0 = *(const float4*)&us[q * 4];
            float4 u1 = *(const float4*)&us[128 + q * 4];
            float4 u2 = *(const float4*)&us[256 + q * 4];
            a0 += x.x * u0.x + x.y * u0.y + x.z * u0.z + x.w * u0.w;
            a1 += x.x * u1.x + x.y * u1.y + x.z * u1.z + x.w * u1.w;
            a2 += x.x * u2.x + x.y * u2.y + x.z * u2.z + x.w * u2.w;
        }
        float e0 = a0 + shc[0] + sher[0]; e0 = (e0 > 0.f) ? e0 : 0.2f * e0;
        float e1 = a1 + shc[1] + sher[1]; e1 = (e1 > 0.f) ? e1 : 0.2f * e1;
        float e2 = a2 + shc[2] + sher[2]; e2 = (e2 > 0.f) ? e2 : 0.2f * e2;
        se[tid] = e0; se[128 + tid] = e1; se[256 + tid] = e2;
    }
    __syncthreads();
    // warp-parallel max per head (exact)
    if (tid < 96) {
        int h = tid >> 5, lane = tid & 31;
        float m = -1e30f;
        for (int i = lane; i < 128; i += 32) m = fmaxf(m, se[h * 128 + i]);
        for (int off = 16; off > 0; off >>= 1)
            m = fmaxf(m, __shfl_down_sync(0xffffffffu, m, off));
        if (lane == 0) shm[h] = m;
    }
    __syncthreads();
    if (tid < 128) {
        se[tid]       = expf(se[tid] - shm[0]);
        se[128 + tid] = expf(se[128 + tid] - shm[1]);
        se[256 + tid] = expf(se[256 + tid] - shm[2]);
    }
    __syncthreads();
    // warp-parallel sum per head
    if (tid < 96) {
        int h = tid >> 5, lane = tid & 31;
        float s = 0.f;
        for (int i = lane; i < 128; i += 32) s += se[h * 128 + i];
        for (int off = 16; off > 0; off >>= 1) s += __shfl_down_sync(0xffffffffu, s, off);
        if (lane == 0) shs[h] = s;
    }
    __syncthreads();
    if (tid < 128) {
        se[tid]       /= shs[0];
        se[128 + tid] /= shs[1];
        se[256 + tid] /= shs[2];
    }
    __syncthreads();
    // ts: 4-way partial accumulators
    for (int i = tid; i < 384; i += 256) {
        int h = i >> 7, col = i & 127;
        float a0 = 0.f, a1 = 0.f, a2 = 0.f, a3 = 0.f;
        for (int n = 0; n < 128; n += 4) {
            a0 += se[h * 128 + n]     * A[n * 132 + col];
            a1 += se[h * 128 + n + 1] * A[(n + 1) * 132 + col];
            a2 += se[h * 128 + n + 2] * A[(n + 2) * 132 + col];
            a3 += se[h * 128 + n + 3] * A[(n + 3) * 132 + col];
        }
        ts[i] = (a0 + a1) + (a2 + a3);
    }
    __syncthreads();
    // qs: 4-way partials
    for (int i = tid; i < 384; i += 256) {
        int h = i >> 7, o = i & 127;
        float a0 = 0.f, a1 = 0.f, a2 = 0.f, a3 = 0.f;
        for (int dd = 0; dd < 128; dd += 4) {
            a0 += ts[h * 128 + dd]     * Wpp[dd * 128 + o];
            a1 += ts[h * 128 + dd + 1] * Wpp[(dd + 1) * 128 + o];
            a2 += ts[h * 128 + dd + 2] * Wpp[(dd + 2) * 128 + o];
            a3 += ts[h * 128 + dd + 3] * Wpp[(dd + 3) * 128 + o];
        }
        qs[i] = bpp[o] + (a0 + a1) + (a2 + a3);
    }
    __syncthreads();
    // zb: 4-way partials
    for (int i = tid; i < 384; i += 256) {
        int h = i >> 7, o = i & 127;
        float a0 = 0.f, a1 = 0.f, a2 = 0.f, a3 = 0.f;
        for (int k = 0; k < 128; k += 4) {
            a0 += qs[h * 128 + k]     * Wg_in[k * 384 + h * 128 + o];
            a1 += qs[h * 128 + k + 1] * Wg_in[(k + 1) * 384 + h * 128 + o];
            a2 += qs[h * 128 + k + 2] * Wg_in[(k + 2) * 384 + h * 128 + o];
            a3 += qs[h * 128 + k + 3] * Wg_in[(k + 3) * 384 + h * 128 + o];
        }
        zb[i] = bg_in[h * 128 + o] + (a0 + a1) + (a2 + a3);
    }
    __syncthreads();
    if (tid < 128)
        g_p2i[blk * 128 + tid] = (zb[tid] + zb[128 + tid] + zb[256 + tid]) * (1.f / 3.f);
}

// ---------------- hrs GEMM split-K=16: partials ----------------
__global__ void k_hrs_split(const float* __restrict__ A, const float* __restrict__ B) {
    __shared__ float As[16 * 64];
    __shared__ float Bs[16 * 64];
    int tid = threadIdx.x;
    int bm = blockIdx.y * 64, bn = blockIdx.x * 64;
    int kbase = blockIdx.z * 128;
    int tr = tid >> 4, tc = tid & 15;
    int r0 = tr * 4, c0 = tc * 4;
    float acc[4][4] = {};
    for (int k0 = kbase; k0 < kbase + 128; k0 += 16) {
        {
            int m = tid >> 2, kq = (tid & 3) * 4;
            float4 v = *(const float4*)&A[(size_t)(bm + m) * 2048 + k0 + kq];
            As[(kq + 0) * 64 + m] = v.x; As[(kq + 1) * 64 + m] = v.y;
            As[(kq + 2) * 64 + m] = v.z; As[(kq + 3) * 64 + m] = v.w;
        }
        {
            int k = tid >> 4, n4 = (tid & 15) * 4;
            *(float4*)&Bs[k * 64 + n4] = *(const float4*)&B[(size_t)(k0 + k) * 128 + bn + n4];
        }
        __syncthreads();
        #pragma unroll
        for (int k = 0; k < 16; k++) {
            float a0 = As[k * 64 + r0 + 0], a1 = As[k * 64 + r0 + 1];
            float a2 = As[k * 64 + r0 + 2], a3 = As[k * 64 + r0 + 3];
            float4 b = *(const float4*)&Bs[k * 64 + c0];
            acc[0][0] += a0 * b.x; acc[0][1] += a0 * b.y; acc[0][2] += a0 * b.z; acc[0][3] += a0 * b.w;
            acc[1][0] += a1 * b.x; acc[1][1] += a1 * b.y; acc[1][2] += a1 * b.z; acc[1][3] += a1 * b.w;
            acc[2][0] += a2 * b.x; acc[2][1] += a2 * b.y; acc[2][2] += a2 * b.z; acc[2][3] += a2 * b.w;
            acc[3][0] += a3 * b.x; acc[3][1] += a3 * b.y; acc[3][2] += a3 * b.z; acc[3][3] += a3 * b.w;
        }
        __syncthreads();
    }
    float* P = g_part + (size_t)blockIdx.z * NB * 128;
    #pragma unroll
    for (int i = 0; i < 4; i++) {
        float4 o = {acc[i][0], acc[i][1], acc[i][2], acc[i][3]};
        *(float4*)(P + (size_t)(bm + r0 + i) * 128 + bn + c0) = o;
    }
}

// ---------------- hrs reduce + ph + i2p: 4 parcels/block, 512 threads, smem weights, 4-way ILP ----------------
__global__ void __launch_bounds__(512, 1)
k_hrsph(const float* __restrict__ bhrs,
        const float* __restrict__ Wph, const float* __restrict__ bph) {
    extern __shared__ float W[];          // 128*128 floats = 64KB
    __shared__ float row[4][128], row2[4][128];
    const int g = threadIdx.x >> 7;
    const int t = threadIdx.x & 127;
    const int b = blockIdx.x * 4 + g;
    {
        const float4* S = (const float4*)Wph;
        float4* D = (float4*)W;
        for (int i = threadIdx.x; i < 128 * 32; i += 512) D[i] = S[i];
    }
    {
        float v = bhrs[t];
        #pragma unroll
        for (int z = 0; z < 16; z++)
            v += g_part[(size_t)z * NB * 128 + b * 128 + t];
        g_hrs[b * 128 + t] = v;
        row[g][t] = v;
    }
    __syncthreads();
    {   // ph = row @ Wph + bph, 4-way partials
        float a0 = 0.f, a1 = 0.f, a2 = 0.f, a3 = 0.f;
        for (int k = 0; k < 128; k += 4) {
            a0 += row[g][k]     * W[k * 128 + t];
            a1 += row[g][k + 1] * W[(k + 1) * 128 + t];
            a2 += row[g][k + 2] * W[(k + 2) * 128 + t];
            a3 += row[g][k + 3] * W[(k + 3) * 128 + t];
        }
        float q = bph[t] + (a0 + a1) + (a2 + a3);
        g_ph[b * 128 + t] = q;
        row2[g][t] = q;
    }
    __syncthreads();
    {
        const float4* S = (const float4*)g_wavg;
        float4* D = (float4*)W;
        for (int i = threadIdx.x; i < 128 * 32; i += 512) D[i] = S[i];
    }
    __syncthreads();
    {   // i2p = ph @ wavg + bavg, 4-way partials
        float a0 = 0.f, a1 = 0.f, a2 = 0.f, a3 = 0.f;
        for (int k = 0; k < 128; k += 4) {
            a0 += row2[g][k]     * W[k * 128 + t];
            a1 += row2[g][k + 1] * W[(k + 1) * 128 + t];
            a2 += row2[g][k + 2] * W[(k + 2) * 128 + t];
            a3 += row2[g][k + 3] * W[(k + 3) * 128 + t];
        }
        g_i2p[b * 128 + t] = g_bavg[t] + (a0 + a1) + (a2 + a3);
    }
}

// ---------------- med = (F F^T + 1)/2, 32x32 tiles (256 blocks) ----------------
__global__ void k_med(float* __restrict__ med) {
    __shared__ float As[32 * 20], Bs[32 * 20];
    int tid = threadIdx.x;   // 256
    int bm = blockIdx.y * 32, bn = blockIdx.x * 32;
    int tr = tid >> 4, tc = tid & 15;
    int r0 = tr * 2, c0 = tc * 2;
    float acc[2][2] = {};
    for (int k0 = 0; k0 < 256; k0 += 16) {
        if (tid < 128) {
            int m = tid >> 2, kq = (tid & 3) * 4;
            *(float4*)&As[m * 20 + kq] = *(const float4*)&g_F[(bm + m) * 256 + k0 + kq];
        } else {
            int m = (tid - 128) >> 2, kq = ((tid - 128) & 3) * 4;
            *(float4*)&Bs[m * 20 + kq] = *(const float4*)&g_F[(bn + m) * 256 + k0 + kq];
        }
        __syncthreads();
        #pragma unroll
        for (int kq = 0; kq < 16; kq += 4) {
            float4 av[2], bv[2];
            #pragma unroll
            for (int i = 0; i < 2; i++) av[i] = *(const float4*)&As[(r0 + i) * 20 + kq];
            #pragma unroll
            for (int j = 0; j < 2; j++) bv[j] = *(const float4*)&Bs[(c0 + j) * 20 + kq];
            #pragma unroll
            for (int i = 0; i < 2; i++)
                #pragma unroll
                for (int j = 0; j < 2; j++)
                    acc[i][j] += av[i].x * bv[j].x + av[i].y * bv[j].y
                               + av[i].z * bv[j].z + av[i].w * bv[j].w;
        }
        __syncthreads();
    }
    #pragma unroll
    for (int i = 0; i < 2; i++)
        #pragma unroll
        for (int j = 0; j < 2; j++)
            med[(bm + r0 + i) * NB + bn + c0 + j] = (acc[i][j] + 1.f) * 0.5f;
}

// ---------------- row compaction: neighbor list + dinv ----------------
__global__ void k_nbr(const float* __restrict__ T0, const float* __restrict__ med) {
    __shared__ int sc[128];
    int i = blockIdx.x, t = threadIdx.x;
    float T = T0[0];
    int jbase = t * 4;
    int loc[4];
    int c = 0;
    #pragma unroll
    for (int q = 0; q < 4; q++) {
        int j = jbase + q;
        float m = med[i * NB + j];
        if (m >= T || j == i) loc[c++] = j;
    }
    sc[t] = c;
    __syncthreads();
    for (int off = 1; off < 128; off <<= 1) {
        int v = (t >= off) ? sc[t - off] : 0;
        __syncthreads();
        sc[t] += v;
        __syncthreads();
    }
    int o = sc[t] - c;
    for (int q = 0; q < c; q++) g_nbr[i * NB + o + q] = loc[q];
    if (t == 127) {
        g_nnz[i] = sc[127];
        g_dinv[i] = rsqrtf((float)sc[127]);
    }
}

// AH[i] = dinv_i * sum_{j in nbr(i)} dinv_j * [hrs_j | pool_j]
__global__ void k_AH() {
    int i = blockIdx.x, t = threadIdx.x;   // 256 threads
    const float* srcp = (t < 128) ? g_hrs : g_pool;
    int cc = t & 127;
    int nnz = g_nnz[i];
    float acc = 0.f;
    for (int p = 0; p < nnz; p++) {
        int j = g_nbr[i * NB + p];
        acc += g_dinv[j] * srcp[j * 128 + cc];
    }
    g_AH[i * 256 + t] = g_dinv[i] * acc;
}

// ---------------- hrsagg/poiagg, 32x32 tiles, z selects ----------------
__global__ void k_gemmZ(const float* __restrict__ Wh1, const float* __restrict__ bh1,
                        const float* __restrict__ Wp1, const float* __restrict__ bp1) {
    __shared__ float As[32 * 20], Bs[16 * 32];
    int z = blockIdx.z;
    const float* Bw = z ? Wp1 : Wh1;
    const float* bias = z ? bp1 : bh1;
    float* Cout = z ? g_poiagg : g_hrsagg;
    const float* Arow = g_AH + z * 128;   // row stride 256
    int tid = threadIdx.x;   // 256
    int bm = blockIdx.y * 32, bn = blockIdx.x * 32;
    int tr = tid >> 4, tc = tid & 15;
    int r0 = tr * 2, c0 = tc * 2;
    float acc[2][2] = {};
    for (int k0 = 0; k0 < 128; k0 += 16) {
        if (tid < 128) {
            int m = tid >> 2, kq = (tid & 3) * 4;
            *(float4*)&As[m * 20 + kq] = *(const float4*)&Arow[(size_t)(bm + m) * 256 + k0 + kq];
        } else {
            int k = (tid - 128) >> 3, n4 = ((tid - 128) & 7) * 4;
            *(float4*)&Bs[k * 32 + n4] = *(const float4*)&Bw[(size_t)(k0 + k) * 128 + bn + n4];
        }
        __syncthreads();
        #pragma unroll
        for (int k = 0; k < 16; k++) {
            float a0 = As[r0 * 20 + k], a1 = As[(r0 + 1) * 20 + k];
            float b0 = Bs[k * 32 + c0], b1 = Bs[k * 32 + c0 + 1];
            acc[0][0] += a0 * b0; acc[0][1] += a0 * b1;
            acc[1][0] += a1 * b0; acc[1][1] += a1 * b1;
        }
        __syncthreads();
    }
    #pragma unroll
    for (int i = 0; i < 2; i++) {
        Cout[(size_t)(bm + r0 + i) * 128 + bn + c0]     = acc[i][0] + bias[bn + c0];
        Cout[(size_t)(bm + r0 + i) * 128 + bn + c0 + 1] = acc[i][1] + bias[bn + c0 + 1];
    }
}

// ---------------- GAT algebraic prep (block per head) ----------------
__global__ void k_prep(const float* __restrict__ Wg_in, const float* __restrict__ al,
                       const float* __restrict__ ar, const float* __restrict__ Wpp,
                       const float* __restrict__ bpp) {
    __shared__ float vs[128];
    __shared__ float red[128];
    int h = blockIdx.x, d = threadIdx.x;   // 3 x 128
    float v = 0.f, r = 0.f;
    for (int c = 0; c < 128; c++) {
        float w = Wg_in[d * 384 + h * 128 + c];
        v += w * al[h * 128 + c];
        r += w * ar[h * 128 + c];
    }
    vs[d] = v;
    g_rv[h * 128 + d] = r;
    __syncthreads();
    float u = 0.f;
    for (int kk = 0; kk < 128; kk++) u += Wpp[d * 128 + kk] * vs[kk];
    g_u[h * 128 + d] = u;
    red[d] = bpp[d] * vs[d];
    __syncthreads();
    for (int off = 64; off > 0; off >>= 1) {
        if (d < off) red[d] += red[d + off];
        __syncthreads();
    }
    if (d == 0) g_ch[h] = red[0];
}

// ---------------- final concat + fc ----------------
__global__ void k_final(const float* __restrict__ Wfc, const float* __restrict__ bfc,
                        float* __restrict__ out) {
    __shared__ float s[512];
    __shared__ float red[128];
    int b = blockIdx.x, t = threadIdx.x;
    s[t]       = g_i2p[b * 128 + t];
    s[128 + t] = g_poiagg[b * 128 + t];
    s[256 + t] = g_p2i[b * 128 + t];
    s[384 + t] = g_hrsagg[b * 128 + t];
    __syncthreads();
    int o = t & 15, p = t >> 4;
    float acc = 0.f;
    for (int j = p * 64; j < p * 64 + 64; j++) acc += s[j] * Wfc[j * 16 + o];
    red[t] = acc;
    __syncthreads();
    if (t < 16) {
        float v = bfc[t];
        for (int pp = 0; pp < 8; pp++) v += red[pp * 16 + t];
        out[b * 16 + t] = v;
    }
}

// ---------------- launch ----------------
extern "C" void kernel_launch(void* const* d_in, const int* in_sizes, int n_in,
                              void* d_out, int out_size) {
    const float* poi_x = (const float*)d_in[0];
    const float* img   = (const float*)d_in[1];
    const int*   edges = (const int*)d_in[2];
    const float* T0    = (const float*)d_in[4];
    const float* W1 = (const float*)d_in[5];
    const float* b1 = (const float*)d_in[6];
    const float* W2 = (const float*)d_in[7];
    const float* b2 = (const float*)d_in[8];
    const float* Whrs = (const float*)d_in[9];
    const float* bhrs = (const float*)d_in[10];
    const float* Wph = (const float*)d_in[11];
    const float* bph = (const float*)d_in[12];
    const float* Wpp = (const float*)d_in[13];
    const float* bpp = (const float*)d_in[14];
    const float* Wg_in = (const float*)d_in[15];
    const float* al_in = (const float*)d_in[16];
    const float* ar_in = (const float*)d_in[17];
    const float* bg_in = (const float*)d_in[18];
    const float* Wg_w  = (const float*)d_in[19];
    const float* bg_w  = (const float*)d_in[22];
    const float* Wh1 = (const float*)d_in[23];
    const float* bh1 = (const float*)d_in[24];
    const float* Wp1 = (const float*)d_in[25];
    const float* bp1 = (const float*)d_in[26];
    const float* Wfc = (const float*)d_in[27];
    const float* bfc = (const float*)d_in[28];
    float* out = (float*)d_out;

    float* p_med;
    cudaGetSymbolAddress((void**)&p_med, g_med);
    float* med = (out_size >= NB * 16 + NB * NB) ? (out + NB * 16) : p_med;

    const int SMEMM = (128 * 132 + 64 * 128) * 4;   // 100352 -> 2 CTAs/SM
    cudaFuncSetAttribute((const void*)k_mega,
                         cudaFuncAttributeMaxDynamicSharedMemorySize, SMEMM);
    const int SMEMH = 128 * 128 * 4;                // 65536
    cudaFuncSetAttribute((const void*)k_hrsph,
                         cudaFuncAttributeMaxDynamicSharedMemorySize, SMEMH);

    const int* e_src = edges;
    const int* e_dst = edges + NE;

    // graph prep (+wavg fused into zero)
    k_zero<<<64, 256>>>(Wg_w, bg_w);
    k_scatter<<<NE / 4 / 256, 256>>>(e_src, e_dst);

    // hrs encoder + projections + GAT algebra
    k_hrs_split<<<dim3(2, 8, 16), 256>>>(img, Whrs);
    k_hrsph<<<NB / 4, 512, SMEMH>>>(bhrs, Wph, bph);
    k_prep<<<3, 128>>>(Wg_in, al_in, ar_in, Wpp, bpp);

    // fused gcn1+gcn2+pool+F+gat+p2i  (2 CTAs/SM)
    k_mega<<<NB, 256, SMEMM>>>(poi_x, W1, b1, W2, b2, Wpp, bpp, Wg_in, bg_in);

    // parcel similarity
    k_med<<<dim3(16, 16), 256>>>(med);
    k_nbr<<<NB, 128>>>(T0, med);
    k_AH<<<NB, 256>>>();
    k_gemmZ<<<dim3(4, 16, 2), 256>>>(Wh1, bh1, Wp1, bp1);

    // final
    k_final<<<NB, 128>>>(Wfc, bfc, out);
}

// round 16
// speedup vs baseline: 1.0236x; 1.0236x over previous
#include <cuda_runtime.h>

#define NB 512
#define PPAR 128
#define NN 65536
#define NE 524288
#define CAP 48

// ---------------- scratch (device globals; no allocation) ----------------
__device__ int   g_cnt[NN];
__device__ unsigned char g_slot[(size_t)NN * CAP];
__device__ float g_hrs[NB * 128];
__device__ float g_part[16 * NB * 128];
__device__ float g_pool[NB * 128];
__device__ float g_F[NB * 256];
__device__ float g_med[NB * NB];     // fallback if out buffer lacks med space
__device__ float g_dinv[NB];
__device__ int   g_nnz[NB];
__device__ int   g_nbr[NB * NB];
__device__ float g_AH[NB * 256];
__device__ float g_hrsagg[NB * 128];
__device__ float g_poiagg[NB * 128];
__device__ float g_ph[NB * 128];
__device__ float g_er[NB * 3];
__device__ float g_u[3 * 128];
__device__ float g_rv[3 * 128];
__device__ float g_ch[3];
__device__ float g_p2i[NB * 128];
__device__ float g_i2p[NB * 128];
__device__ float g_wavg[128 * 128];
__device__ float g_bavg[128];

// ---------------- zero counts (int4) + wavg/bavg (fused) ----------------
__global__ void k_zero(const float* __restrict__ Wg_w, const float* __restrict__ bg_w) {
    int i = blockIdx.x * blockDim.x + threadIdx.x;   // 16384 threads
    if (i < NN / 4) ((int4*)g_cnt)[i] = make_int4(0, 0, 0, 0);
    if (i < 128 * 128) {
        int k = i >> 7, c = i & 127;
        g_wavg[i] = (Wg_w[k * 384 + c] + Wg_w[k * 384 + 128 + c] + Wg_w[k * 384 + 256 + c])
                    * (1.f / 3.f);
    }
    if (i < 128)
        g_bavg[i] = (bg_w[i] + bg_w[128 + i] + bg_w[256 + i]) * (1.f / 3.f);
}

__global__ void k_scatter(const int* __restrict__ src, const int* __restrict__ dst) {
    int idx = blockIdx.x * blockDim.x + threadIdx.x;   // NE/4 threads
    if (idx < NE / 4) {
        int4 s4 = ((const int4*)src)[idx];
        int4 d4 = ((const int4*)dst)[idx];
        int ss[4] = {s4.x, s4.y, s4.z, s4.w};
        int dd[4] = {d4.x, d4.y, d4.z, d4.w};
        #pragma unroll
        for (int q = 0; q < 4; q++) {
            int d = dd[q];
            int pos = atomicAdd(&g_cnt[d], 1);
            if (pos < CAP)
                g_slot[(size_t)d * CAP + pos] = (unsigned char)(ss[q] & 127);
        }
    }
}

// ---------------- MEGA: gcn1 + gcn2 + pool + F-normalize + GAT + p2i ----------------
// 2 regions, 100KB dyn smem, 2 CTAs/SM.
__global__ void __launch_bounds__(256, 2)
k_mega(const float* __restrict__ poi_x,
       const float* __restrict__ W1, const float* __restrict__ b1,
       const float* __restrict__ W2, const float* __restrict__ b2,
       const float* __restrict__ Wpp, const float* __restrict__ bpp,
       const float* __restrict__ Wg_in, const float* __restrict__ bg_in) {
    extern __shared__ float sm[];
    float* A = sm;
    float* C = sm + 128 * 132;
    __shared__ float snrm[128];
    __shared__ int scnt[128];
    __shared__ float shm[3], shs[3], sher[3], shc[3];
    const int tid = threadIdx.x;
    const int blk = blockIdx.x;
    const int base = blk * 128;

    if (tid < 128) {
        int c = g_cnt[base + tid];
        snrm[tid] = rsqrtf((float)c + 1.0f);
        scnt[tid] = (c > CAP) ? CAP : c;
    }
    {   // W1 -> C (64x128)
        const float4* W4 = (const float4*)W1;
        float4* C4 = (float4*)C;
        for (int i = tid; i < 64 * 32; i += 256) C4[i] = W4[i];
    }
    __syncthreads();
    {   // X * norm -> A (stride 68)
        const float4* in4 = (const float4*)(poi_x + (size_t)base * 64);
        for (int i = tid; i < 128 * 16; i += 256) {
            int r = i >> 4, c4 = i & 15;
            float4 v = in4[i];
            float nr = snrm[r];
            v.x *= nr; v.y *= nr; v.z *= nr; v.w *= nr;
            *(float4*)&A[r * 68 + c4 * 4] = v;
        }
    }
    __syncthreads();
    const int d = tid >> 1;
    const int tr = tid >> 4, tc = tid & 15;
    const int r0 = tr * 8, cc0 = tc * 8;

    // ---- agg1 (K=64) into registers ----
    {
        const int c0 = (tid & 1) * 32;
        float racc[32];
        #pragma unroll
        for (int q = 0; q < 8; q++) {
            float4 v = *(const float4*)&A[d * 68 + c0 + q * 4];
            racc[q * 4 + 0] = v.x; racc[q * 4 + 1] = v.y;
            racc[q * 4 + 2] = v.z; racc[q * 4 + 3] = v.w;
        }
        const int cnt = scnt[d];
        const unsigned char* sl = g_slot + (size_t)(base + d) * CAP;
        for (int e = 0; e < cnt; e++) {
            int s = sl[e];
            #pragma unroll
            for (int q = 0; q < 8; q++) {
                float4 v = *(const float4*)&A[s * 68 + c0 + q * 4];
                racc[q * 4 + 0] += v.x; racc[q * 4 + 1] += v.y;
                racc[q * 4 + 2] += v.z; racc[q * 4 + 3] += v.w;
            }
        }
        float nr = snrm[d];
        __syncthreads();   // all X reads done -> safe to overwrite A
        #pragma unroll
        for (int c = 0; c < 32; c++) A[(c0 + c) * 132 + d] = racc[c] * nr;   // AGt1
    }
    __syncthreads();

    float vacc[8][8];
    // ---- GEMM1: vacc = AGt1(A) @ W1(C) ----
    #pragma unroll
    for (int i = 0; i < 8; i++)
        #pragma unroll
        for (int j = 0; j < 8; j++) vacc[i][j] = 0.f;
    for (int k = 0; k < 64; k++) {
        float4 a0 = *(const float4*)&A[k * 132 + r0];
        float4 a1 = *(const float4*)&A[k * 132 + r0 + 4];
        float4 b0 = *(const float4*)&C[k * 128 + cc0];
        float4 b1v = *(const float4*)&C[k * 128 + cc0 + 4];
        float av[8] = {a0.x, a0.y, a0.z, a0.w, a1.x, a1.y, a1.z, a1.w};
        float bv[8] = {b0.x, b0.y, b0.z, b0.w, b1v.x, b1v.y, b1v.z, b1v.w};
        #pragma unroll
        for (int i = 0; i < 8; i++)
            #pragma unroll
            for (int j = 0; j < 8; j++) vacc[i][j] += av[i] * bv[j];
    }
    __syncthreads();   // AGt1 + W1 reads done
    {   // h1 = relu(vacc + b1) * snrm[row] -> A
        float bv[8];
        #pragma unroll
        for (int j = 0; j < 8; j++) bv[j] = b1[cc0 + j];
        #pragma unroll
        for (int i = 0; i < 8; i++) {
            float nr2 = snrm[r0 + i];
            #pragma unroll
            for (int j = 0; j < 8; j++)
                vacc[i][j] = fmaxf(vacc[i][j] + bv[j], 0.f) * nr2;
            float4 o0 = {vacc[i][0], vacc[i][1], vacc[i][2], vacc[i][3]};
            float4 o1 = {vacc[i][4], vacc[i][5], vacc[i][6], vacc[i][7]};
            *(float4*)&A[(r0 + i) * 132 + cc0] = o0;
            *(float4*)&A[(r0 + i) * 132 + cc0 + 4] = o1;
        }
    }
    __syncthreads();   // h1 visible

    // ---- W2 half1 -> C, agg2 (K=128) into registers ----
    {
        const float4* W4 = (const float4*)W2;
        float4* C4 = (float4*)C;
        for (int i = tid; i < 64 * 32; i += 256) C4[i] = W4[i];
    }
    {
        const int c0 = (tid & 1) * 64;
        float racc[64];
        #pragma unroll
        for (int q = 0; q < 16; q++) {
            float4 v = *(const float4*)&A[d * 132 + c0 + q * 4];
            racc[q * 4 + 0] = v.x; racc[q * 4 + 1] = v.y;
            racc[q * 4 + 2] = v.z; racc[q * 4 + 3] = v.w;
        }
        const int cnt = scnt[d];
        const unsigned char* sl = g_slot + (size_t)(base + d) * CAP;
        for (int e = 0; e < cnt; e++) {
            int s = sl[e];
            #pragma unroll
            for (int q = 0; q < 16; q++) {
                float4 v = *(const float4*)&A[s * 132 + c0 + q * 4];
                racc[q * 4 + 0] += v.x; racc[q * 4 + 1] += v.y;
                racc[q * 4 + 2] += v.z; racc[q * 4 + 3] += v.w;
            }
        }
        float nr = snrm[d];
        __syncthreads();   // all h1 reads done -> safe to overwrite A
        #pragma unroll
        for (int c = 0; c < 64; c++) A[(c0 + c) * 132 + d] = racc[c] * nr;   // AGt2
    }
    __syncthreads();

    // ---- GEMM2 pass1: k = 0..63 ----
    #pragma unroll
    for (int i = 0; i < 8; i++)
        #pragma unroll
        for (int j = 0; j < 8; j++) vacc[i][j] = 0.f;
    for (int k = 0; k < 64; k++) {
        float4 a0 = *(const float4*)&A[k * 132 + r0];
        float4 a1 = *(const float4*)&A[k * 132 + r0 + 4];
        float4 b0 = *(const float4*)&C[k * 128 + cc0];
        float4 b1v = *(const float4*)&C[k * 128 + cc0 + 4];
        float av[8] = {a0.x, a0.y, a0.z, a0.w, a1.x, a1.y, a1.z, a1.w};
        float bv[8] = {b0.x, b0.y, b0.z, b0.w, b1v.x, b1v.y, b1v.z, b1v.w};
        #pragma unroll
        for (int i = 0; i < 8; i++)
            #pragma unroll
            for (int j = 0; j < 8; j++) vacc[i][j] += av[i] * bv[j];
    }
    __syncthreads();
    {   // W2 half2 -> C
        const float4* W4 = (const float4*)(W2 + 64 * 128);
        float4* C4 = (float4*)C;
        for (int i = tid; i < 64 * 32; i += 256) C4[i] = W4[i];
    }
    __syncthreads();
    // ---- GEMM2 pass2: k = 64..127 ----
    for (int k = 64; k < 128; k++) {
        float4 a0 = *(const float4*)&A[k * 132 + r0];
        float4 a1 = *(const float4*)&A[k * 132 + r0 + 4];
        float4 b0 = *(const float4*)&C[(k - 64) * 128 + cc0];
        float4 b1v = *(const float4*)&C[(k - 64) * 128 + cc0 + 4];
        float av[8] = {a0.x, a0.y, a0.z, a0.w, a1.x, a1.y, a1.z, a1.w};
        float bv[8] = {b0.x, b0.y, b0.z, b0.w, b1v.x, b1v.y, b1v.z, b1v.w};
        #pragma unroll
        for (int i = 0; i < 8; i++)
            #pragma unroll
            for (int j = 0; j < 8; j++) vacc[i][j] += av[i] * bv[j];
    }
    __syncthreads();
    {   // poi = vacc + b2 -> A
        float bv[8];
        #pragma unroll
        for (int j = 0; j < 8; j++) bv[j] = b2[cc0 + j];
        #pragma unroll
        for (int i = 0; i < 8; i++) {
            #pragma unroll
            for (int j = 0; j < 8; j++) vacc[i][j] += bv[j];
            float4 o0 = {vacc[i][0], vacc[i][1], vacc[i][2], vacc[i][3]};
            float4 o1 = {vacc[i][4], vacc[i][5], vacc[i][6], vacc[i][7]};
            *(float4*)&A[(r0 + i) * 132 + cc0] = o0;
            *(float4*)&A[(r0 + i) * 132 + cc0 + 4] = o1;
        }
    }
    __syncthreads();

    // ---- scratch layout in C ----
    float* P   = C;          // [16][128]
    float* us  = C + 2048;   // 384
    float* se  = C + 2944;   // 384
    float* ts  = C + 3328;   // 384
    float* qs  = C + 3712;   // 384
    float* fv  = C + 4096;   // 256
    float* red = C + 4352;   // 256
    float* zb  = C;          // alias P

    #pragma unroll
    for (int j = 0; j < 8; j++) {
        float s = 0.f;
        #pragma unroll
        for (int i = 0; i < 8; i++) s += vacc[i][j];
        P[tr * 128 + cc0 + j] = s;
    }
    for (int i = tid; i < 384; i += 256) us[i] = g_u[i];
    if (tid < 3) { shc[tid] = g_ch[tid]; sher[tid] = g_er[blk * 3 + tid]; }
    __syncthreads();
    if (tid < 128) {
        float s = 0.f;
        #pragma unroll
        for (int r = 0; r < 16; r++) s += P[r * 128 + tid];
        float pv = s * (1.f / 128.f);
        g_pool[blk * 128 + tid] = pv;
        fv[128 + tid] = pv;
        fv[tid] = g_hrs[blk * 128 + tid];
    }
    __syncthreads();
    {
        float v = fv[tid];
        red[tid] = v * v;
        __syncthreads();
        for (int off = 128; off > 0; off >>= 1) {
            if (tid < off) red[tid] += red[tid + off];
            __syncthreads();
        }
        float inv = rsqrtf(red[0]);
        g_F[blk * 256 + tid] = v * inv;
    }

    if (tid < 128) {
        float a0 = 0.f, a1 = 0.f, a2 = 0.f;
        #pragma unroll
        for (int q = 0; q < 32; q++) {
            float4 x = *(const float4*)&A[tid * 132 + q * 4];
            float4 u0 = *(const float4*)&us[q * 4];
            float4 u1 = *(const float4*)&us[128 + q * 4];
            float4 u2 = *(const float4*)&us[256 + q * 4];
            a0 += x.x * u0.x + x.y * u0.y + x.z * u0.z + x.w * u0.w;
            a1 += x.x * u1.x + x.y * u1.y + x.z * u1.z + x.w * u1.w;
            a2 += x.x * u2.x + x.y * u2.y + x.z * u2.z + x.w * u2.w;
        }
        float e0 = a0 + shc[0] + sher[0]; e0 = (e0 > 0.f) ? e0 : 0.2f * e0;
        float e1 = a1 + shc[1] + sher[1]; e1 = (e1 > 0.f) ? e1 : 0.2f * e1;
        float e2 = a2 + shc[2] + sher[2]; e2 = (e2 > 0.f) ? e2 : 0.2f * e2;
        se[tid] = e0; se[128 + tid] = e1; se[256 + tid] = e2;
    }
    __syncthreads();
    if (tid < 3) {
        float m = -1e30f;
        for (int i = 0; i < 128; i++) m = fmaxf(m, se[tid * 128 + i]);
        shm[tid] = m;
    }
    __syncthreads();
    if (tid < 128) {
        se[tid]       = expf(se[tid] - shm[0]);
        se[128 + tid] = expf(se[128 + tid] - shm[1]);
        se[256 + tid] = expf(se[256 + tid] - shm[2]);
    }
    __syncthreads();
    if (tid < 3) {
        float s = 0.f;
        for (int i = 0; i < 128; i++) s += se[tid * 128 + i];
        shs[tid] = s;
    }
    __syncthreads();
    if (tid < 128) {
        se[tid]       /= shs[0];
        se[128 + tid] /= shs[1];
        se[256 + tid] /= shs[2];
    }
    __syncthreads();
    for (int i = tid; i < 384; i += 256) {
        int h = i >> 7, col = i & 127;
        float acc = 0.f;
        for (int n = 0; n < 128; n++) acc += se[h * 128 + n] * A[n * 132 + col];
        ts[i] = acc;
    }
    __syncthreads();
    for (int i = tid; i < 384; i += 256) {
        int h = i >> 7, o = i & 127;
        float q = bpp[o];
        for (int dd = 0; dd < 128; dd++) q += ts[h * 128 + dd] * Wpp[dd * 128 + o];
        qs[i] = q;
    }
    __syncthreads();
    for (int i = tid; i < 384; i += 256) {
        int h = i >> 7, o = i & 127;
        float zz = bg_in[h * 128 + o];
        for (int k = 0; k < 128; k++) zz += qs[h * 128 + k] * Wg_in[k * 384 + h * 128 + o];
        zb[i] = zz;
    }
    __syncthreads();
    if (tid < 128)
        g_p2i[blk * 128 + tid] = (zb[tid] + zb[128 + tid] + zb[256 + tid]) * (1.f / 3.f);
}

// ---------------- hrs GEMM split-K=16: partials ----------------
__global__ void k_hrs_split(const float* __restrict__ A, const float* __restrict__ B) {
    __shared__ float As[16 * 64];
    __shared__ float Bs[16 * 64];
    int tid = threadIdx.x;
    int bm = blockIdx.y * 64, bn = blockIdx.x * 64;
    int kbase = blockIdx.z * 128;
    int tr = tid >> 4, tc = tid & 15;
    int r0 = tr * 4, c0 = tc * 4;
    float acc[4][4] = {};
    for (int k0 = kbase; k0 < kbase + 128; k0 += 16) {
        {
            int m = tid >> 2, kq = (tid & 3) * 4;
            float4 v = *(const float4*)&A[(size_t)(bm + m) * 2048 + k0 + kq];
            As[(kq + 0) * 64 + m] = v.x; As[(kq + 1) * 64 + m] = v.y;
            As[(kq + 2) * 64 + m] = v.z; As[(kq + 3) * 64 + m] = v.w;
        }
        {
            int k = tid >> 4, n4 = (tid & 15) * 4;
            *(float4*)&Bs[k * 64 + n4] = *(const float4*)&B[(size_t)(k0 + k) * 128 + bn + n4];
        }
        __syncthreads();
        #pragma unroll
        for (int k = 0; k < 16; k++) {
            float a0 = As[k * 64 + r0 + 0], a1 = As[k * 64 + r0 + 1];
            float a2 = As[k * 64 + r0 + 2], a3 = As[k * 64 + r0 + 3];
            float4 b = *(const float4*)&Bs[k * 64 + c0];
            acc[0][0] += a0 * b.x; acc[0][1] += a0 * b.y; acc[0][2] += a0 * b.z; acc[0][3] += a0 * b.w;
            acc[1][0] += a1 * b.x; acc[1][1] += a1 * b.y; acc[1][2] += a1 * b.z; acc[1][3] += a1 * b.w;
            acc[2][0] += a2 * b.x; acc[2][1] += a2 * b.y; acc[2][2] += a2 * b.z; acc[2][3] += a2 * b.w;
            acc[3][0] += a3 * b.x; acc[3][1] += a3 * b.y; acc[3][2] += a3 * b.z; acc[3][3] += a3 * b.w;
        }
        __syncthreads();
    }
    float* P = g_part + (size_t)blockIdx.z * NB * 128;
    #pragma unroll
    for (int i = 0; i < 4; i++) {
        float4 o = {acc[i][0], acc[i][1], acc[i][2], acc[i][3]};
        *(float4*)(P + (size_t)(bm + r0 + i) * 128 + bn + c0) = o;
    }
}

// ---------------- hrs reduce + ph + er + i2p: 4 parcels/block, 512 threads, smem weights ----------------
__global__ void __launch_bounds__(512, 1)
k_hrsph(const float* __restrict__ bhrs,
        const float* __restrict__ Wph, const float* __restrict__ bph) {
    extern __shared__ float W[];          // 128*128 floats = 64KB
    __shared__ float row[4][128], row2[4][128];
    const int g = threadIdx.x >> 7;
    const int t = threadIdx.x & 127;
    const int b = blockIdx.x * 4 + g;
    {
        const float4* S = (const float4*)Wph;
        float4* D = (float4*)W;
        for (int i = threadIdx.x; i < 128 * 32; i += 512) D[i] = S[i];
    }
    {
        float v = bhrs[t];
        #pragma unroll
        for (int z = 0; z < 16; z++)
            v += g_part[(size_t)z * NB * 128 + b * 128 + t];
        g_hrs[b * 128 + t] = v;
        row[g][t] = v;
    }
    __syncthreads();
    {
        float q = bph[t];
        for (int k = 0; k < 128; k++) q += row[g][k] * W[k * 128 + t];
        g_ph[b * 128 + t] = q;
        row2[g][t] = q;
    }
    __syncthreads();
    // er[b][h] = ph . rv[h]  (3 warps per group; g_rv from k_prep, which runs earlier)
    if (t < 96) {
        int h = t >> 5, lane = t & 31;
        float s = 0.f;
        for (int j = lane; j < 128; j += 32) s += row2[g][j] * g_rv[h * 128 + j];
        for (int off = 16; off > 0; off >>= 1) s += __shfl_down_sync(0xffffffffu, s, off);
        if (lane == 0) g_er[b * 3 + h] = s;
    }
    {   // stage wavg over W
        const float4* S = (const float4*)g_wavg;
        float4* D = (float4*)W;
        for (int i = threadIdx.x; i < 128 * 32; i += 512) D[i] = S[i];
    }
    __syncthreads();
    {
        float z2 = g_bavg[t];
        for (int k = 0; k < 128; k++) z2 += row2[g][k] * W[k * 128 + t];
        g_i2p[b * 128 + t] = z2;
    }
}

// ---------------- med = (F F^T + 1)/2, 32x32 tiles (256 blocks) ----------------
__global__ void k_med(float* __restrict__ med) {
    __shared__ float As[32 * 20], Bs[32 * 20];
    int tid = threadIdx.x;   // 256
    int bm = blockIdx.y * 32, bn = blockIdx.x * 32;
    int tr = tid >> 4, tc = tid & 15;
    int r0 = tr * 2, c0 = tc * 2;
    float acc[2][2] = {};
    for (int k0 = 0; k0 < 256; k0 += 16) {
        if (tid < 128) {
            int m = tid >> 2, kq = (tid & 3) * 4;
            *(float4*)&As[m * 20 + kq] = *(const float4*)&g_F[(bm + m) * 256 + k0 + kq];
        } else {
            int m = (tid - 128) >> 2, kq = ((tid - 128) & 3) * 4;
            *(float4*)&Bs[m * 20 + kq] = *(const float4*)&g_F[(bn + m) * 256 + k0 + kq];
        }
        __syncthreads();
        #pragma unroll
        for (int kq = 0; kq < 16; kq += 4) {
            float4 av[2], bv[2];
            #pragma unroll
            for (int i = 0; i < 2; i++) av[i] = *(const float4*)&As[(r0 + i) * 20 + kq];
            #pragma unroll
            for (int j = 0; j < 2; j++) bv[j] = *(const float4*)&Bs[(c0 + j) * 20 + kq];
            #pragma unroll
            for (int i = 0; i < 2; i++)
                #pragma unroll
                for (int j = 0; j < 2; j++)
                    acc[i][j] += av[i].x * bv[j].x + av[i].y * bv[j].y
                               + av[i].z * bv[j].z + av[i].w * bv[j].w;
        }
        __syncthreads();
    }
    #pragma unroll
    for (int i = 0; i < 2; i++)
        #pragma unroll
        for (int j = 0; j < 2; j++)
            med[(bm + r0 + i) * NB + bn + c0 + j] = (acc[i][j] + 1.f) * 0.5f;
}

// ---------------- row compaction: neighbor list + dinv ----------------
__global__ void k_nbr(const float* __restrict__ T0, const float* __restrict__ med) {
    __shared__ int sc[128];
    int i = blockIdx.x, t = threadIdx.x;
    float T = T0[0];
    int jbase = t * 4;
    int loc[4];
    int c = 0;
    #pragma unroll
    for (int q = 0; q < 4; q++) {
        int j = jbase + q;
        float m = med[i * NB + j];
        if (m >= T || j == i) loc[c++] = j;
    }
    sc[t] = c;
    __syncthreads();
    for (int off = 1; off < 128; off <<= 1) {
        int v = (t >= off) ? sc[t - off] : 0;
        __syncthreads();
        sc[t] += v;
        __syncthreads();
    }
    int o = sc[t] - c;
    for (int q = 0; q < c; q++) g_nbr[i * NB + o + q] = loc[q];
    if (t == 127) {
        g_nnz[i] = sc[127];
        g_dinv[i] = rsqrtf((float)sc[127]);
    }
}

// AH[i] = dinv_i * sum_{j in nbr(i)} dinv_j * [hrs_j | pool_j]
__global__ void k_AH() {
    int i = blockIdx.x, t = threadIdx.x;   // 256 threads
    const float* srcp = (t < 128) ? g_hrs : g_pool;
    int cc = t & 127;
    int nnz = g_nnz[i];
    float acc = 0.f;
    for (int p = 0; p < nnz; p++) {
        int j = g_nbr[i * NB + p];
        acc += g_dinv[j] * srcp[j * 128 + cc];
    }
    g_AH[i * 256 + t] = g_dinv[i] * acc;
}

// ---------------- hrsagg/poiagg, 32x32 tiles, z selects ----------------
__global__ void k_gemmZ(const float* __restrict__ Wh1, const float* __restrict__ bh1,
                        const float* __restrict__ Wp1, const float* __restrict__ bp1) {
    __shared__ float As[32 * 20], Bs[16 * 32];
    int z = blockIdx.z;
    const float* Bw = z ? Wp1 : Wh1;
    const float* bias = z ? bp1 : bh1;
    float* Cout = z ? g_poiagg : g_hrsagg;
    const float* Arow = g_AH + z * 128;   // row stride 256
    int tid = threadIdx.x;   // 256
    int bm = blockIdx.y * 32, bn = blockIdx.x * 32;
    int tr = tid >> 4, tc = tid & 15;
    int r0 = tr * 2, c0 = tc * 2;
    float acc[2][2] = {};
    for (int k0 = 0; k0 < 128; k0 += 16) {
        if (tid < 128) {
            int m = tid >> 2, kq = (tid & 3) * 4;
            *(float4*)&As[m * 20 + kq] = *(const float4*)&Arow[(size_t)(bm + m) * 256 + k0 + kq];
        } else {
            int k = (tid - 128) >> 3, n4 = ((tid - 128) & 7) * 4;
            *(float4*)&Bs[k * 32 + n4] = *(const float4*)&Bw[(size_t)(k0 + k) * 128 + bn + n4];
        }
        __syncthreads();
        #pragma unroll
        for (int k = 0; k < 16; k++) {
            float a0 = As[r0 * 20 + k], a1 = As[(r0 + 1) * 20 + k];
            float b0 = Bs[k * 32 + c0], b1 = Bs[k * 32 + c0 + 1];
            acc[0][0] += a0 * b0; acc[0][1] += a0 * b1;
            acc[1][0] += a1 * b0; acc[1][1] += a1 * b1;
        }
        __syncthreads();
    }
    #pragma unroll
    for (int i = 0; i < 2; i++) {
        Cout[(size_t)(bm + r0 + i) * 128 + bn + c0]     = acc[i][0] + bias[bn + c0];
        Cout[(size_t)(bm + r0 + i) * 128 + bn + c0 + 1] = acc[i][1] + bias[bn + c0 + 1];
    }
}

// ---------------- GAT algebraic prep (block per head) ----------------
__global__ void k_prep(const float* __restrict__ Wg_in, const float* __restrict__ al,
                       const float* __restrict__ ar, const float* __restrict__ Wpp,
                       const float* __restrict__ bpp) {
    __shared__ float vs[128];
    __shared__ float red[128];
    int h = blockIdx.x, d = threadIdx.x;   // 3 x 128
    float v = 0.f, r = 0.f;
    for (int c = 0; c < 128; c++) {
        float w = Wg_in[d * 384 + h * 128 + c];
        v += w * al[h * 128 + c];
        r += w * ar[h * 128 + c];
    }
    vs[d] = v;
    g_rv[h * 128 + d] = r;
    __syncthreads();
    float u = 0.f;
    for (int kk = 0; kk < 128; kk++) u += Wpp[d * 128 + kk] * vs[kk];
    g_u[h * 128 + d] = u;
    red[d] = bpp[d] * vs[d];
    __syncthreads();
    for (int off = 64; off > 0; off >>= 1) {
        if (d < off) red[d] += red[d + off];
        __syncthreads();
    }
    if (d == 0) g_ch[h] = red[0];
}

// ---------------- final concat + fc ----------------
__global__ void k_final(const float* __restrict__ Wfc, const float* __restrict__ bfc,
                        float* __restrict__ out) {
    __shared__ float s[512];
    __shared__ float red[128];
    int b = blockIdx.x, t = threadIdx.x;
    s[t]       = g_i2p[b * 128 + t];
    s[128 + t] = g_poiagg[b * 128 + t];
    s[256 + t] = g_p2i[b * 128 + t];
    s[384 + t] = g_hrsagg[b * 128 + t];
    __syncthreads();
    int o = t & 15, p = t >> 4;
    float acc = 0.f;
    for (int j = p * 64; j < p * 64 + 64; j++) acc += s[j] * Wfc[j * 16 + o];
    red[t] = acc;
    __syncthreads();
    if (t < 16) {
        float v = bfc[t];
        for (int pp = 0; pp < 8; pp++) v += red[pp * 16 + t];
        out[b * 16 + t] = v;
    }
}

// ---------------- launch ----------------
extern "C" void kernel_launch(void* const* d_in, const int* in_sizes, int n_in,
                              void* d_out, int out_size) {
    const float* poi_x = (const float*)d_in[0];
    const float* img   = (const float*)d_in[1];
    const int*   edges = (const int*)d_in[2];
    const float* T0    = (const float*)d_in[4];
    const float* W1 = (const float*)d_in[5];
    const float* b1 = (const float*)d_in[6];
    const float* W2 = (const float*)d_in[7];
    const float* b2 = (const float*)d_in[8];
    const float* Whrs = (const float*)d_in[9];
    const float* bhrs = (const float*)d_in[10];
    const float* Wph = (const float*)d_in[11];
    const float* bph = (const float*)d_in[12];
    const float* Wpp = (const float*)d_in[13];
    const float* bpp = (const float*)d_in[14];
    const float* Wg_in = (const float*)d_in[15];
    const float* al_in = (const float*)d_in[16];
    const float* ar_in = (const float*)d_in[17];
    const float* bg_in = (const float*)d_in[18];
    const float* Wg_w  = (const float*)d_in[19];
    const float* bg_w  = (const float*)d_in[22];
    const float* Wh1 = (const float*)d_in[23];
    const float* bh1 = (const float*)d_in[24];
    const float* Wp1 = (const float*)d_in[25];
    const float* bp1 = (const float*)d_in[26];
    const float* Wfc = (const float*)d_in[27];
    const float* bfc = (const float*)d_in[28];
    float* out = (float*)d_out;

    float* p_med;
    cudaGetSymbolAddress((void**)&p_med, g_med);
    float* med = (out_size >= NB * 16 + NB * NB) ? (out + NB * 16) : p_med;

    const int SMEMM = (128 * 132 + 64 * 128) * 4;   // 100352 -> 2 CTAs/SM
    cudaFuncSetAttribute((const void*)k_mega,
                         cudaFuncAttributeMaxDynamicSharedMemorySize, SMEMM);
    const int SMEMH = 128 * 128 * 4;                // 65536
    cudaFuncSetAttribute((const void*)k_hrsph,
                         cudaFuncAttributeMaxDynamicSharedMemorySize, SMEMH);

    const int* e_src = edges;
    const int* e_dst = edges + NE;

    // graph prep (+wavg fused into zero)
    k_zero<<<64, 256>>>(Wg_w, bg_w);
    k_scatter<<<NE / 4 / 256, 256>>>(e_src, e_dst);

    // hrs encoder + projections + GAT algebra (prep before hrsph: hrsph consumes g_rv)
    k_hrs_split<<<dim3(2, 8, 16), 256>>>(img, Whrs);
    k_prep<<<3, 128>>>(Wg_in, al_in, ar_in, Wpp, bpp);
    k_hrsph<<<NB / 4, 512, SMEMH>>>(bhrs, Wph, bph);

    // fused gcn1+gcn2+pool+F+gat+p2i  (2 CTAs/SM)
    k_mega<<<NB, 256, SMEMM>>>(poi_x, W1, b1, W2, b2, Wpp, bpp, Wg_in, bg_in);

    // parcel similarity
    k_med<<<dim3(16, 16), 256>>>(med);
    k_nbr<<<NB, 128>>>(T0, med);
    k_AH<<<NB, 256>>>();
    k_gemmZ<<<dim3(4, 16, 2), 256>>>(Wh1, bh1, Wp1, bp1);

    // final
    k_final<<<NB, 128>>>(Wfc, bfc, out);
}

// round 17
// speedup vs baseline: 1.0767x; 1.0519x over previous
#include <cuda_runtime.h>

#define NB 512
#define PPAR 128
#define NN 65536
#define NE 524288
#define CAP 48

// ---------------- scratch (device globals; no allocation) ----------------
__device__ int   g_cnt[NN];
__device__ unsigned char g_slot[(size_t)NN * CAP];
__device__ float g_hrs[NB * 128];
__device__ float g_part[16 * NB * 128];
__device__ float g_pool[NB * 128];
__device__ float g_F[NB * 256];
__device__ float g_med[NB * NB];     // fallback if out buffer lacks med space
__device__ float g_dinv[NB];
__device__ int   g_nnz[NB];
__device__ int   g_nbr[NB * NB];
__device__ float g_AH[NB * 256];
__device__ float g_hrsagg[NB * 128];
__device__ float g_poiagg[NB * 128];
__device__ float g_ph[NB * 128];
__device__ float g_er[NB * 3];
__device__ float g_u[3 * 128];
__device__ float g_rv[3 * 128];
__device__ float g_ch[3];
__device__ float g_p2i[NB * 128];
__device__ float g_i2p[NB * 128];
__device__ float g_wavg[128 * 128];
__device__ float g_bavg[128];

// ---------------- zero counts (int4) + wavg/bavg (fused) ----------------
__global__ void k_zero(const float* __restrict__ Wg_w, const float* __restrict__ bg_w) {
    int i = blockIdx.x * blockDim.x + threadIdx.x;   // 16384 threads
    if (i < NN / 4) ((int4*)g_cnt)[i] = make_int4(0, 0, 0, 0);
    if (i < 128 * 128) {
        int k = i >> 7, c = i & 127;
        g_wavg[i] = (Wg_w[k * 384 + c] + Wg_w[k * 384 + 128 + c] + Wg_w[k * 384 + 256 + c])
                    * (1.f / 3.f);
    }
    if (i < 128)
        g_bavg[i] = (bg_w[i] + bg_w[128 + i] + bg_w[256 + i]) * (1.f / 3.f);
}

__global__ void k_scatter(const int* __restrict__ src, const int* __restrict__ dst) {
    int idx = blockIdx.x * blockDim.x + threadIdx.x;   // NE/4 threads
    if (idx < NE / 4) {
        int4 s4 = ((const int4*)src)[idx];
        int4 d4 = ((const int4*)dst)[idx];
        int ss[4] = {s4.x, s4.y, s4.z, s4.w};
        int dd[4] = {d4.x, d4.y, d4.z, d4.w};
        #pragma unroll
        for (int q = 0; q < 4; q++) {
            int d = dd[q];
            int pos = atomicAdd(&g_cnt[d], 1);
            if (pos < CAP)
                g_slot[(size_t)d * CAP + pos] = (unsigned char)(ss[q] & 127);
        }
    }
}

// ---------------- MEGA: gcn1 + gcn2 + pool + F-normalize + GAT + p2i ----------------
// 2 regions, 100KB dyn smem, 2 CTAs/SM.
__global__ void __launch_bounds__(256, 2)
k_mega(const float* __restrict__ poi_x,
       const float* __restrict__ W1, const float* __restrict__ b1,
       const float* __restrict__ W2, const float* __restrict__ b2,
       const float* __restrict__ Wpp, const float* __restrict__ bpp,
       const float* __restrict__ Wg_in, const float* __restrict__ bg_in) {
    extern __shared__ float sm[];
    float* A = sm;
    float* C = sm + 128 * 132;
    __shared__ float snrm[128];
    __shared__ int scnt[128];
    __shared__ float shm[3], shs[3], sher[3], shc[3];
    const int tid = threadIdx.x;
    const int blk = blockIdx.x;
    const int base = blk * 128;

    if (tid < 128) {
        int c = g_cnt[base + tid];
        snrm[tid] = rsqrtf((float)c + 1.0f);
        scnt[tid] = (c > CAP) ? CAP : c;
    }
    {   // W1 -> C (64x128)
        const float4* W4 = (const float4*)W1;
        float4* C4 = (float4*)C;
        for (int i = tid; i < 64 * 32; i += 256) C4[i] = W4[i];
    }
    __syncthreads();
    {   // X * norm -> A (stride 68)
        const float4* in4 = (const float4*)(poi_x + (size_t)base * 64);
        for (int i = tid; i < 128 * 16; i += 256) {
            int r = i >> 4, c4 = i & 15;
            float4 v = in4[i];
            float nr = snrm[r];
            v.x *= nr; v.y *= nr; v.z *= nr; v.w *= nr;
            *(float4*)&A[r * 68 + c4 * 4] = v;
        }
    }
    __syncthreads();
    const int d = tid >> 1;
    const int tr = tid >> 4, tc = tid & 15;
    const int r0 = tr * 8, cc0 = tc * 8;

    // ---- agg1 (K=64) into registers ----
    {
        const int c0 = (tid & 1) * 32;
        float racc[32];
        #pragma unroll
        for (int q = 0; q < 8; q++) {
            float4 v = *(const float4*)&A[d * 68 + c0 + q * 4];
            racc[q * 4 + 0] = v.x; racc[q * 4 + 1] = v.y;
            racc[q * 4 + 2] = v.z; racc[q * 4 + 3] = v.w;
        }
        const int cnt = scnt[d];
        const unsigned char* sl = g_slot + (size_t)(base + d) * CAP;
        for (int e = 0; e < cnt; e++) {
            int s = sl[e];
            #pragma unroll
            for (int q = 0; q < 8; q++) {
                float4 v = *(const float4*)&A[s * 68 + c0 + q * 4];
                racc[q * 4 + 0] += v.x; racc[q * 4 + 1] += v.y;
                racc[q * 4 + 2] += v.z; racc[q * 4 + 3] += v.w;
            }
        }
        float nr = snrm[d];
        __syncthreads();   // all X reads done -> safe to overwrite A
        #pragma unroll
        for (int c = 0; c < 32; c++) A[(c0 + c) * 132 + d] = racc[c] * nr;   // AGt1
    }
    __syncthreads();

    float vacc[8][8];
    // ---- GEMM1: vacc = AGt1(A) @ W1(C) ----
    #pragma unroll
    for (int i = 0; i < 8; i++)
        #pragma unroll
        for (int j = 0; j < 8; j++) vacc[i][j] = 0.f;
    for (int k = 0; k < 64; k++) {
        float4 a0 = *(const float4*)&A[k * 132 + r0];
        float4 a1 = *(const float4*)&A[k * 132 + r0 + 4];
        float4 b0 = *(const float4*)&C[k * 128 + cc0];
        float4 b1v = *(const float4*)&C[k * 128 + cc0 + 4];
        float av[8] = {a0.x, a0.y, a0.z, a0.w, a1.x, a1.y, a1.z, a1.w};
        float bv[8] = {b0.x, b0.y, b0.z, b0.w, b1v.x, b1v.y, b1v.z, b1v.w};
        #pragma unroll
        for (int i = 0; i < 8; i++)
            #pragma unroll
            for (int j = 0; j < 8; j++) vacc[i][j] += av[i] * bv[j];
    }
    __syncthreads();   // AGt1 + W1 reads done
    {   // h1 = relu(vacc + b1) * snrm[row] -> A
        float bv[8];
        #pragma unroll
        for (int j = 0; j < 8; j++) bv[j] = b1[cc0 + j];
        #pragma unroll
        for (int i = 0; i < 8; i++) {
            float nr2 = snrm[r0 + i];
            #pragma unroll
            for (int j = 0; j < 8; j++)
                vacc[i][j] = fmaxf(vacc[i][j] + bv[j], 0.f) * nr2;
            float4 o0 = {vacc[i][0], vacc[i][1], vacc[i][2], vacc[i][3]};
            float4 o1 = {vacc[i][4], vacc[i][5], vacc[i][6], vacc[i][7]};
            *(float4*)&A[(r0 + i) * 132 + cc0] = o0;
            *(float4*)&A[(r0 + i) * 132 + cc0 + 4] = o1;
        }
    }
    __syncthreads();   // h1 visible

    // ---- W2 half1 -> C, agg2 (K=128) into registers ----
    {
        const float4* W4 = (const float4*)W2;
        float4* C4 = (float4*)C;
        for (int i = tid; i < 64 * 32; i += 256) C4[i] = W4[i];
    }
    {
        const int c0 = (tid & 1) * 64;
        float racc[64];
        #pragma unroll
        for (int q = 0; q < 16; q++) {
            float4 v = *(const float4*)&A[d * 132 + c0 + q * 4];
            racc[q * 4 + 0] = v.x; racc[q * 4 + 1] = v.y;
            racc[q * 4 + 2] = v.z; racc[q * 4 + 3] = v.w;
        }
        const int cnt = scnt[d];
        const unsigned char* sl = g_slot + (size_t)(base + d) * CAP;
        for (int e = 0; e < cnt; e++) {
            int s = sl[e];
            #pragma unroll
            for (int q = 0; q < 16; q++) {
                float4 v = *(const float4*)&A[s * 132 + c0 + q * 4];
                racc[q * 4 + 0] += v.x; racc[q * 4 + 1] += v.y;
                racc[q * 4 + 2] += v.z; racc[q * 4 + 3] += v.w;
            }
        }
        float nr = snrm[d];
        __syncthreads();   // all h1 reads done -> safe to overwrite A
        #pragma unroll
        for (int c = 0; c < 64; c++) A[(c0 + c) * 132 + d] = racc[c] * nr;   // AGt2
    }
    __syncthreads();

    // ---- GEMM2 pass1: k = 0..63 ----
    #pragma unroll
    for (int i = 0; i < 8; i++)
        #pragma unroll
        for (int j = 0; j < 8; j++) vacc[i][j] = 0.f;
    for (int k = 0; k < 64; k++) {
        float4 a0 = *(const float4*)&A[k * 132 + r0];
        float4 a1 = *(const float4*)&A[k * 132 + r0 + 4];
        float4 b0 = *(const float4*)&C[k * 128 + cc0];
        float4 b1v = *(const float4*)&C[k * 128 + cc0 + 4];
        float av[8] = {a0.x, a0.y, a0.z, a0.w, a1.x, a1.y, a1.z, a1.w};
        float bv[8] = {b0.x, b0.y, b0.z, b0.w, b1v.x, b1v.y, b1v.z, b1v.w};
        #pragma unroll
        for (int i = 0; i < 8; i++)
            #pragma unroll
            for (int j = 0; j < 8; j++) vacc[i][j] += av[i] * bv[j];
    }
    __syncthreads();
    {   // W2 half2 -> C
        const float4* W4 = (const float4*)(W2 + 64 * 128);
        float4* C4 = (float4*)C;
        for (int i = tid; i < 64 * 32; i += 256) C4[i] = W4[i];
    }
    __syncthreads();
    // ---- GEMM2 pass2: k = 64..127 ----
    for (int k = 64; k < 128; k++) {
        float4 a0 = *(const float4*)&A[k * 132 + r0];
        float4 a1 = *(const float4*)&A[k * 132 + r0 + 4];
        float4 b0 = *(const float4*)&C[(k - 64) * 128 + cc0];
        float4 b1v = *(const float4*)&C[(k - 64) * 128 + cc0 + 4];
        float av[8] = {a0.x, a0.y, a0.z, a0.w, a1.x, a1.y, a1.z, a1.w};
        float bv[8] = {b0.x, b0.y, b0.z, b0.w, b1v.x, b1v.y, b1v.z, b1v.w};
        #pragma unroll
        for (int i = 0; i < 8; i++)
            #pragma unroll
            for (int j = 0; j < 8; j++) vacc[i][j] += av[i] * bv[j];
    }
    __syncthreads();
    {   // poi = vacc + b2 -> A
        float bv[8];
        #pragma unroll
        for (int j = 0; j < 8; j++) bv[j] = b2[cc0 + j];
        #pragma unroll
        for (int i = 0; i < 8; i++) {
            #pragma unroll
            for (int j = 0; j < 8; j++) vacc[i][j] += bv[j];
            float4 o0 = {vacc[i][0], vacc[i][1], vacc[i][2], vacc[i][3]};
            float4 o1 = {vacc[i][4], vacc[i][5], vacc[i][6], vacc[i][7]};
            *(float4*)&A[(r0 + i) * 132 + cc0] = o0;
            *(float4*)&A[(r0 + i) * 132 + cc0 + 4] = o1;
        }
    }
    __syncthreads();

    // ---- scratch layout in C ----
    float* P   = C;          // [16][128]
    float* us  = C + 2048;   // 384
    float* se  = C + 2944;   // 384
    float* ts  = C + 3328;   // 384
    float* qs  = C + 3712;   // 384
    float* fv  = C + 4096;   // 256
    float* red = C + 4352;   // 256
    float* zb  = C;          // alias P

    #pragma unroll
    for (int j = 0; j < 8; j++) {
        float s = 0.f;
        #pragma unroll
        for (int i = 0; i < 8; i++) s += vacc[i][j];
        P[tr * 128 + cc0 + j] = s;
    }
    for (int i = tid; i < 384; i += 256) us[i] = g_u[i];
    if (tid < 3) { shc[tid] = g_ch[tid]; sher[tid] = g_er[blk * 3 + tid]; }
    __syncthreads();
    if (tid < 128) {
        float s = 0.f;
        #pragma unroll
        for (int r = 0; r < 16; r++) s += P[r * 128 + tid];
        float pv = s * (1.f / 128.f);
        g_pool[blk * 128 + tid] = pv;
        fv[128 + tid] = pv;
        fv[tid] = g_hrs[blk * 128 + tid];
    }
    __syncthreads();
    {
        float v = fv[tid];
        red[tid] = v * v;
        __syncthreads();
        for (int off = 128; off > 0; off >>= 1) {
            if (tid < off) red[tid] += red[tid + off];
            __syncthreads();
        }
        float inv = rsqrtf(red[0]);
        g_F[blk * 256 + tid] = v * inv;
    }

    if (tid < 128) {
        float a0 = 0.f, a1 = 0.f, a2 = 0.f;
        #pragma unroll
        for (int q = 0; q < 32; q++) {
            float4 x = *(const float4*)&A[tid * 132 + q * 4];
            float4 u0 = *(const float4*)&us[q * 4];
            float4 u1 = *(const float4*)&us[128 + q * 4];
            float4 u2 = *(const float4*)&us[256 + q * 4];
            a0 += x.x * u0.x + x.y * u0.y + x.z * u0.z + x.w * u0.w;
            a1 += x.x * u1.x + x.y * u1.y + x.z * u1.z + x.w * u1.w;
            a2 += x.x * u2.x + x.y * u2.y + x.z * u2.z + x.w * u2.w;
        }
        float e0 = a0 + shc[0] + sher[0]; e0 = (e0 > 0.f) ? e0 : 0.2f * e0;
        float e1 = a1 + shc[1] + sher[1]; e1 = (e1 > 0.f) ? e1 : 0.2f * e1;
        float e2 = a2 + shc[2] + sher[2]; e2 = (e2 > 0.f) ? e2 : 0.2f * e2;
        se[tid] = e0; se[128 + tid] = e1; se[256 + tid] = e2;
    }
    __syncthreads();
    if (tid < 3) {
        float m = -1e30f;
        for (int i = 0; i < 128; i++) m = fmaxf(m, se[tid * 128 + i]);
        shm[tid] = m;
    }
    __syncthreads();
    if (tid < 128) {
        se[tid]       = expf(se[tid] - shm[0]);
        se[128 + tid] = expf(se[128 + tid] - shm[1]);
        se[256 + tid] = expf(se[256 + tid] - shm[2]);
    }
    __syncthreads();
    if (tid < 3) {
        float s = 0.f;
        for (int i = 0; i < 128; i++) s += se[tid * 128 + i];
        shs[tid] = s;
    }
    __syncthreads();
    if (tid < 128) {
        se[tid]       /= shs[0];
        se[128 + tid] /= shs[1];
        se[256 + tid] /= shs[2];
    }
    __syncthreads();
    for (int i = tid; i < 384; i += 256) {
        int h = i >> 7, col = i & 127;
        float acc = 0.f;
        for (int n = 0; n < 128; n++) acc += se[h * 128 + n] * A[n * 132 + col];
        ts[i] = acc;
    }
    __syncthreads();
    for (int i = tid; i < 384; i += 256) {
        int h = i >> 7, o = i & 127;
        float q = bpp[o];
        for (int dd = 0; dd < 128; dd++) q += ts[h * 128 + dd] * Wpp[dd * 128 + o];
        qs[i] = q;
    }
    __syncthreads();
    for (int i = tid; i < 384; i += 256) {
        int h = i >> 7, o = i & 127;
        float zz = bg_in[h * 128 + o];
        for (int k = 0; k < 128; k++) zz += qs[h * 128 + k] * Wg_in[k * 384 + h * 128 + o];
        zb[i] = zz;
    }
    __syncthreads();
    if (tid < 128)
        g_p2i[blk * 128 + tid] = (zb[tid] + zb[128 + tid] + zb[256 + tid]) * (1.f / 3.f);
}

// ---------------- hrs GEMM split-K=16: partials ----------------
__global__ void k_hrs_split(const float* __restrict__ A, const float* __restrict__ B) {
    __shared__ float As[16 * 64];
    __shared__ float Bs[16 * 64];
    int tid = threadIdx.x;
    int bm = blockIdx.y * 64, bn = blockIdx.x * 64;
    int kbase = blockIdx.z * 128;
    int tr = tid >> 4, tc = tid & 15;
    int r0 = tr * 4, c0 = tc * 4;
    float acc[4][4] = {};
    for (int k0 = kbase; k0 < kbase + 128; k0 += 16) {
        {
            int m = tid >> 2, kq = (tid & 3) * 4;
            float4 v = *(const float4*)&A[(size_t)(bm + m) * 2048 + k0 + kq];
            As[(kq + 0) * 64 + m] = v.x; As[(kq + 1) * 64 + m] = v.y;
            As[(kq + 2) * 64 + m] = v.z; As[(kq + 3) * 64 + m] = v.w;
        }
        {
            int k = tid >> 4, n4 = (tid & 15) * 4;
            *(float4*)&Bs[k * 64 + n4] = *(const float4*)&B[(size_t)(k0 + k) * 128 + bn + n4];
        }
        __syncthreads();
        #pragma unroll
        for (int k = 0; k < 16; k++) {
            float a0 = As[k * 64 + r0 + 0], a1 = As[k * 64 + r0 + 1];
            float a2 = As[k * 64 + r0 + 2], a3 = As[k * 64 + r0 + 3];
            float4 b = *(const float4*)&Bs[k * 64 + c0];
            acc[0][0] += a0 * b.x; acc[0][1] += a0 * b.y; acc[0][2] += a0 * b.z; acc[0][3] += a0 * b.w;
            acc[1][0] += a1 * b.x; acc[1][1] += a1 * b.y; acc[1][2] += a1 * b.z; acc[1][3] += a1 * b.w;
            acc[2][0] += a2 * b.x; acc[2][1] += a2 * b.y; acc[2][2] += a2 * b.z; acc[2][3] += a2 * b.w;
            acc[3][0] += a3 * b.x; acc[3][1] += a3 * b.y; acc[3][2] += a3 * b.z; acc[3][3] += a3 * b.w;
        }
        __syncthreads();
    }
    float* P = g_part + (size_t)blockIdx.z * NB * 128;
    #pragma unroll
    for (int i = 0; i < 4; i++) {
        float4 o = {acc[i][0], acc[i][1], acc[i][2], acc[i][3]};
        *(float4*)(P + (size_t)(bm + r0 + i) * 128 + bn + c0) = o;
    }
}

// ---------------- hrs reduce + ph + er + i2p: 4 parcels/block, 512 threads, smem weights ----------------
__global__ void __launch_bounds__(512, 1)
k_hrsph(const float* __restrict__ bhrs,
        const float* __restrict__ Wph, const float* __restrict__ bph) {
    extern __shared__ float W[];          // 128*128 floats = 64KB
    __shared__ float row[4][128], row2[4][128];
    const int g = threadIdx.x >> 7;
    const int t = threadIdx.x & 127;
    const int b = blockIdx.x * 4 + g;
    {
        const float4* S = (const float4*)Wph;
        float4* D = (float4*)W;
        for (int i = threadIdx.x; i < 128 * 32; i += 512) D[i] = S[i];
    }
    {
        float v = bhrs[t];
        #pragma unroll
        for (int z = 0; z < 16; z++)
            v += g_part[(size_t)z * NB * 128 + b * 128 + t];
        g_hrs[b * 128 + t] = v;
        row[g][t] = v;
    }
    __syncthreads();
    {
        float q = bph[t];
        for (int k = 0; k < 128; k++) q += row[g][k] * W[k * 128 + t];
        g_ph[b * 128 + t] = q;
        row2[g][t] = q;
    }
    __syncthreads();
    // er[b][h] = ph . rv[h]  (3 warps per group; g_rv from k_prep, which runs earlier)
    if (t < 96) {
        int h = t >> 5, lane = t & 31;
        float s = 0.f;
        for (int j = lane; j < 128; j += 32) s += row2[g][j] * g_rv[h * 128 + j];
        for (int off = 16; off > 0; off >>= 1) s += __shfl_down_sync(0xffffffffu, s, off);
        if (lane == 0) g_er[b * 3 + h] = s;
    }
    {   // stage wavg over W
        const float4* S = (const float4*)g_wavg;
        float4* D = (float4*)W;
        for (int i = threadIdx.x; i < 128 * 32; i += 512) D[i] = S[i];
    }
    __syncthreads();
    {
        float z2 = g_bavg[t];
        for (int k = 0; k < 128; k++) z2 += row2[g][k] * W[k * 128 + t];
        g_i2p[b * 128 + t] = z2;
    }
}

// ---------------- med = (F F^T + 1)/2, 32x32 tiles (256 blocks) ----------------
__global__ void k_med(float* __restrict__ med) {
    __shared__ float As[32 * 20], Bs[32 * 20];
    int tid = threadIdx.x;   // 256
    int bm = blockIdx.y * 32, bn = blockIdx.x * 32;
    int tr = tid >> 4, tc = tid & 15;
    int r0 = tr * 2, c0 = tc * 2;
    float acc[2][2] = {};
    for (int k0 = 0; k0 < 256; k0 += 16) {
        if (tid < 128) {
            int m = tid >> 2, kq = (tid & 3) * 4;
            *(float4*)&As[m * 20 + kq] = *(const float4*)&g_F[(bm + m) * 256 + k0 + kq];
        } else {
            int m = (tid - 128) >> 2, kq = ((tid - 128) & 3) * 4;
            *(float4*)&Bs[m * 20 + kq] = *(const float4*)&g_F[(bn + m) * 256 + k0 + kq];
        }
        __syncthreads();
        #pragma unroll
        for (int kq = 0; kq < 16; kq += 4) {
            float4 av[2], bv[2];
            #pragma unroll
            for (int i = 0; i < 2; i++) av[i] = *(const float4*)&As[(r0 + i) * 20 + kq];
            #pragma unroll
            for (int j = 0; j < 2; j++) bv[j] = *(const float4*)&Bs[(c0 + j) * 20 + kq];
            #pragma unroll
            for (int i = 0; i < 2; i++)
                #pragma unroll
                for (int j = 0; j < 2; j++)
                    acc[i][j] += av[i].x * bv[j].x + av[i].y * bv[j].y
                               + av[i].z * bv[j].z + av[i].w * bv[j].w;
        }
        __syncthreads();
    }
    #pragma unroll
    for (int i = 0; i < 2; i++)
        #pragma unroll
        for (int j = 0; j < 2; j++)
            med[(bm + r0 + i) * NB + bn + c0 + j] = (acc[i][j] + 1.f) * 0.5f;
}

// ---------------- row compaction: neighbor list + dinv ----------------
__global__ void k_nbr(const float* __restrict__ T0, const float* __restrict__ med) {
    __shared__ int sc[128];
    int i = blockIdx.x, t = threadIdx.x;
    float T = T0[0];
    int jbase = t * 4;
    int loc[4];
    int c = 0;
    #pragma unroll
    for (int q = 0; q < 4; q++) {
        int j = jbase + q;
        float m = med[i * NB + j];
        if (m >= T || j == i) loc[c++] = j;
    }
    sc[t] = c;
    __syncthreads();
    for (int off = 1; off < 128; off <<= 1) {
        int v = (t >= off) ? sc[t - off] : 0;
        __syncthreads();
        sc[t] += v;
        __syncthreads();
    }
    int o = sc[t] - c;
    for (int q = 0; q < c; q++) g_nbr[i * NB + o + q] = loc[q];
    if (t == 127) {
        g_nnz[i] = sc[127];
        g_dinv[i] = rsqrtf((float)sc[127]);
    }
}

// AH[i] = dinv_i * sum_{j in nbr(i)} dinv_j * [hrs_j | pool_j]
__global__ void k_AH() {
    int i = blockIdx.x, t = threadIdx.x;   // 256 threads
    const float* srcp = (t < 128) ? g_hrs : g_pool;
    int cc = t & 127;
    int nnz = g_nnz[i];
    float acc = 0.f;
    for (int p = 0; p < nnz; p++) {
        int j = g_nbr[i * NB + p];
        acc += g_dinv[j] * srcp[j * 128 + cc];
    }
    g_AH[i * 256 + t] = g_dinv[i] * acc;
}

// ---------------- hrsagg/poiagg, 32x32 tiles, z selects ----------------
__global__ void k_gemmZ(const float* __restrict__ Wh1, const float* __restrict__ bh1,
                        const float* __restrict__ Wp1, const float* __restrict__ bp1) {
    __shared__ float As[32 * 20], Bs[16 * 32];
    int z = blockIdx.z;
    const float* Bw = z ? Wp1 : Wh1;
    const float* bias = z ? bp1 : bh1;
    float* Cout = z ? g_poiagg : g_hrsagg;
    const float* Arow = g_AH + z * 128;   // row stride 256
    int tid = threadIdx.x;   // 256
    int bm = blockIdx.y * 32, bn = blockIdx.x * 32;
    int tr = tid >> 4, tc = tid & 15;
    int r0 = tr * 2, c0 = tc * 2;
    float acc[2][2] = {};
    for (int k0 = 0; k0 < 128; k0 += 16) {
        if (tid < 128) {
            int m = tid >> 2, kq = (tid & 3) * 4;
            *(float4*)&As[m * 20 + kq] = *(const float4*)&Arow[(size_t)(bm + m) * 256 + k0 + kq];
        } else {
            int k = (tid - 128) >> 3, n4 = ((tid - 128) & 7) * 4;
            *(float4*)&Bs[k * 32 + n4] = *(const float4*)&Bw[(size_t)(k0 + k) * 128 + bn + n4];
        }
        __syncthreads();
        #pragma unroll
        for (int k = 0; k < 16; k++) {
            float a0 = As[r0 * 20 + k], a1 = As[(r0 + 1) * 20 + k];
            float b0 = Bs[k * 32 + c0], b1 = Bs[k * 32 + c0 + 1];
            acc[0][0] += a0 * b0; acc[0][1] += a0 * b1;
            acc[1][0] += a1 * b0; acc[1][1] += a1 * b1;
        }
        __syncthreads();
    }
    #pragma unroll
    for (int i = 0; i < 2; i++) {
        Cout[(size_t)(bm + r0 + i) * 128 + bn + c0]     = acc[i][0] + bias[bn + c0];
        Cout[(size_t)(bm + r0 + i) * 128 + bn + c0 + 1] = acc[i][1] + bias[bn + c0 + 1];
    }
}

// ---------------- GAT algebraic prep: 3 blocks x 1024 threads, 8 threads/output ----------------
__global__ void __launch_bounds__(1024, 1)
k_prep(const float* __restrict__ Wg_in, const float* __restrict__ al,
       const float* __restrict__ ar, const float* __restrict__ Wpp,
       const float* __restrict__ bpp) {
    __shared__ float vs[128];
    __shared__ float red[128];
    const int h = blockIdx.x;            // head
    const int tid = threadIdx.x;         // 1024
    const int d = tid >> 3;              // output index 0..127
    const int l8 = tid & 7;              // lane within 8-thread group
    // v[d] = Wg_in[d,:]_h . al_h ; r[d] = . ar_h   (8-way strided partials + shfl)
    {
        float v = 0.f, r = 0.f;
        const float* wrow = Wg_in + (size_t)d * 384 + h * 128;
        const float* alh = al + h * 128;
        const float* arh = ar + h * 128;
        for (int c = l8; c < 128; c += 8) {
            float w = wrow[c];
            v += w * alh[c];
            r += w * arh[c];
        }
        #pragma unroll
        for (int off = 4; off > 0; off >>= 1) {
            v += __shfl_down_sync(0xffffffffu, v, off);
            r += __shfl_down_sync(0xffffffffu, r, off);
        }
        if (l8 == 0) { vs[d] = v; g_rv[h * 128 + d] = r; }
    }
    __syncthreads();
    // u[d] = Wpp[d,:] . vs
    {
        float u = 0.f;
        const float* wrow = Wpp + (size_t)d * 128;
        for (int kk = l8; kk < 128; kk += 8) u += wrow[kk] * vs[kk];
        #pragma unroll
        for (int off = 4; off > 0; off >>= 1)
            u += __shfl_down_sync(0xffffffffu, u, off);
        if (l8 == 0) g_u[h * 128 + d] = u;
    }
    // ch = bpp . vs
    if (tid < 128) red[tid] = bpp[tid] * vs[tid];
    __syncthreads();
    for (int off = 64; off > 0; off >>= 1) {
        if (tid < off) red[tid] += red[tid + off];
        __syncthreads();
    }
    if (tid == 0) g_ch[h] = red[0];
}

// ---------------- final concat + fc ----------------
__global__ void k_final(const float* __restrict__ Wfc, const float* __restrict__ bfc,
                        float* __restrict__ out) {
    __shared__ float s[512];
    __shared__ float red[128];
    int b = blockIdx.x, t = threadIdx.x;
    s[t]       = g_i2p[b * 128 + t];
    s[128 + t] = g_poiagg[b * 128 + t];
    s[256 + t] = g_p2i[b * 128 + t];
    s[384 + t] = g_hrsagg[b * 128 + t];
    __syncthreads();
    int o = t & 15, p = t >> 4;
    float acc = 0.f;
    for (int j = p * 64; j < p * 64 + 64; j++) acc += s[j] * Wfc[j * 16 + o];
    red[t] = acc;
    __syncthreads();
    if (t < 16) {
        float v = bfc[t];
        for (int pp = 0; pp < 8; pp++) v += red[pp * 16 + t];
        out[b * 16 + t] = v;
    }
}

// ---------------- launch ----------------
extern "C" void kernel_launch(void* const* d_in, const int* in_sizes, int n_in,
                              void* d_out, int out_size) {
    const float* poi_x = (const float*)d_in[0];
    const float* img   = (const float*)d_in[1];
    const int*   edges = (const int*)d_in[2];
    const float* T0    = (const float*)d_in[4];
    const float* W1 = (const float*)d_in[5];
    const float* b1 = (const float*)d_in[6];
    const float* W2 = (const float*)d_in[7];
    const float* b2 = (const float*)d_in[8];
    const float* Whrs = (const float*)d_in[9];
    const float* bhrs = (const float*)d_in[10];
    const float* Wph = (const float*)d_in[11];
    const float* bph = (const float*)d_in[12];
    const float* Wpp = (const float*)d_in[13];
    const float* bpp = (const float*)d_in[14];
    const float* Wg_in = (const float*)d_in[15];
    const float* al_in = (const float*)d_in[16];
    const float* ar_in = (const float*)d_in[17];
    const float* bg_in = (const float*)d_in[18];
    const float* Wg_w  = (const float*)d_in[19];
    const float* bg_w  = (const float*)d_in[22];
    const float* Wh1 = (const float*)d_in[23];
    const float* bh1 = (const float*)d_in[24];
    const float* Wp1 = (const float*)d_in[25];
    const float* bp1 = (const float*)d_in[26];
    const float* Wfc = (const float*)d_in[27];
    const float* bfc = (const float*)d_in[28];
    float* out = (float*)d_out;

    float* p_med;
    cudaGetSymbolAddress((void**)&p_med, g_med);
    float* med = (out_size >= NB * 16 + NB * NB) ? (out + NB * 16) : p_med;

    const int SMEMM = (128 * 132 + 64 * 128) * 4;   // 100352 -> 2 CTAs/SM
    cudaFuncSetAttribute((const void*)k_mega,
                         cudaFuncAttributeMaxDynamicSharedMemorySize, SMEMM);
    const int SMEMH = 128 * 128 * 4;                // 65536
    cudaFuncSetAttribute((const void*)k_hrsph,
                         cudaFuncAttributeMaxDynamicSharedMemorySize, SMEMH);

    const int* e_src = edges;
    const int* e_dst = edges + NE;

    // graph prep (+wavg fused into zero)
    k_zero<<<64, 256>>>(Wg_w, bg_w);
    k_scatter<<<NE / 4 / 256, 256>>>(e_src, e_dst);

    // hrs encoder + projections + GAT algebra (prep before hrsph: hrsph consumes g_rv)
    k_hrs_split<<<dim3(2, 8, 16), 256>>>(img, Whrs);
    k_prep<<<3, 1024>>>(Wg_in, al_in, ar_in, Wpp, bpp);
    k_hrsph<<<NB / 4, 512, SMEMH>>>(bhrs, Wph, bph);

    // fused gcn1+gcn2+pool+F+gat+p2i  (2 CTAs/SM)
    k_mega<<<NB, 256, SMEMM>>>(poi_x, W1, b1, W2, b2, Wpp, bpp, Wg_in, bg_in);

    // parcel similarity
    k_med<<<dim3(16, 16), 256>>>(med);
    k_nbr<<<NB, 128>>>(T0, med);
    k_AH<<<NB, 256>>>();
    k_gemmZ<<<dim3(4, 16, 2), 256>>>(Wh1, bh1, Wp1, bp1);

    // final
    k_final<<<NB, 128>>>(Wfc, bfc, out);
}